// round 2
// baseline (speedup 1.0000x reference)
#include <cuda_runtime.h>
#include <math_constants.h>

#define NN 50000
#define EE 1600000

// ---------------- scratch (device globals; no allocation allowed) ----------
__device__ float g_feat1[NN * 128];
__device__ float g_rst1 [NN * 128];
__device__ float g_el1  [NN * 4];
__device__ float g_er1  [NN * 4];
__device__ float g_m1   [NN * 4];
__device__ float g_s1   [NN * 4];
__device__ float g_x1   [NN * 32];
__device__ float g_feat2[NN * 16];
__device__ float g_rst2 [NN * 16];
__device__ float g_el2  [NN];
__device__ float g_er2  [NN];
__device__ float g_m2   [NN];
__device__ float g_s2   [NN];

__device__ __forceinline__ void atomicMaxF(float* addr, float v) {
    if (v >= 0.0f) atomicMax((int*)addr, __float_as_int(v));
    else           atomicMin((unsigned int*)addr, __float_as_uint(v));
}

__device__ __forceinline__ float leaky(float v) { return v > 0.0f ? v : 0.2f * v; }

// ---------------- init scratch ---------------------------------------------
__global__ void k_init(int N) {
    int i = blockIdx.x * blockDim.x + threadIdx.x;
    if (i < N * 128) g_rst1[i] = 0.0f;
    if (i < N * 16)  g_rst2[i] = 0.0f;
    if (i < N * 4) { g_m1[i] = -CUDART_INF_F; g_s1[i] = 0.0f; }
    if (i < N)     { g_m2[i] = -CUDART_INF_F; g_s2[i] = 0.0f; }
}

// ---------------- layer 1 GEMM + el/er (fused) ------------------------------
// block = 128 threads = one node row; warp h == head h
__global__ void k_gemm1(const float* __restrict__ x, const float* __restrict__ W,
                        const float* __restrict__ al, const float* __restrict__ ar) {
    __shared__ float xs[128];
    int n = blockIdx.x;
    int t = threadIdx.x;
    xs[t] = x[n * 128 + t];
    __syncthreads();
    float acc = 0.0f;
#pragma unroll 8
    for (int k = 0; k < 128; k++) acc = fmaf(xs[k], W[k * 128 + t], acc);
    g_feat1[n * 128 + t] = acc;
    float pl = acc * al[t];
    float pr = acc * ar[t];
#pragma unroll
    for (int o = 16; o; o >>= 1) {
        pl += __shfl_xor_sync(0xFFFFFFFFu, pl, o);
        pr += __shfl_xor_sync(0xFFFFFFFFu, pr, o);
    }
    if ((t & 31) == 0) {
        int h = t >> 5;
        g_el1[n * 4 + h] = pl;
        g_er1[n * 4 + h] = pr;
    }
}

// ---------------- layer 1 edge max ------------------------------------------
__global__ void k_edge_max1(const int* __restrict__ src, const int* __restrict__ dst, int E) {
    int i = blockIdx.x * blockDim.x + threadIdx.x;
    if (i >= E * 4) return;
    int e = i >> 2, h = i & 3;
    int s = src[e], d = dst[e];
    float v = leaky(g_el1[s * 4 + h] + g_er1[d * 4 + h]);
    atomicMaxF(&g_m1[d * 4 + h], v);
}

// ---------------- layer 1 fused exp + sum + weighted aggregate --------------
// one warp per edge; lane = feature dim within a head
__global__ void k_edge_agg1(const int* __restrict__ src, const int* __restrict__ dst, int E) {
    int w = (blockIdx.x * blockDim.x + threadIdx.x) >> 5;
    int lane = threadIdx.x & 31;
    if (w >= E) return;
    int s = src[w], d = dst[w];
    float ex4 = 0.0f;
    if (lane < 4) {
        float v = leaky(g_el1[s * 4 + lane] + g_er1[d * 4 + lane]);
        ex4 = __expf(v - g_m1[d * 4 + lane]);
        atomicAdd(&g_s1[d * 4 + lane], ex4);
    }
#pragma unroll
    for (int h = 0; h < 4; h++) {
        float ex = __shfl_sync(0xFFFFFFFFu, ex4, h);
        atomicAdd(&g_rst1[d * 128 + h * 32 + lane],
                  ex * g_feat1[s * 128 + h * 32 + lane]);
    }
}

// ---------------- layer 1 finalize: normalize, relu, mean over heads --------
__global__ void k_node1(const float* __restrict__ b1, int N) {
    int i = blockIdx.x * blockDim.x + threadIdx.x;
    if (i >= N * 32) return;
    int n = i >> 5, ddim = i & 31;
    float acc = 0.0f;
#pragma unroll
    for (int h = 0; h < 4; h++) {
        float s = g_s1[n * 4 + h];
        float v = (s > 0.0f) ? g_rst1[n * 128 + h * 32 + ddim] / s : 0.0f;
        v += b1[h * 32 + ddim];
        acc += fmaxf(v, 0.0f);
    }
    g_x1[n * 32 + ddim] = acc * 0.25f;
}

// ---------------- layer 2 GEMM + el2/er2 (fused) ----------------------------
// one warp per node; x1 row distributed across lanes, shfl-broadcast
__global__ void k_gemm2(const float* __restrict__ W2, const float* __restrict__ al2,
                        const float* __restrict__ ar2, int N) {
    int gid = blockIdx.x * blockDim.x + threadIdx.x;
    int n = gid >> 5;
    int lane = threadIdx.x & 31;
    if (n >= N) return;
    float xv = g_x1[n * 32 + lane];
    int t = lane & 15;
    float acc = 0.0f;
#pragma unroll
    for (int k = 0; k < 32; k++)
        acc = fmaf(__shfl_sync(0xFFFFFFFFu, xv, k), W2[k * 16 + t], acc);
    if (lane < 16) g_feat2[n * 16 + t] = acc;
    float pl = (lane < 16) ? acc * al2[t] : 0.0f;
    float pr = (lane < 16) ? acc * ar2[t] : 0.0f;
#pragma unroll
    for (int o = 16; o; o >>= 1) {
        pl += __shfl_xor_sync(0xFFFFFFFFu, pl, o);
        pr += __shfl_xor_sync(0xFFFFFFFFu, pr, o);
    }
    if (lane == 0) { g_el2[n] = pl; g_er2[n] = pr; }
}

// ---------------- layer 2 edge max ------------------------------------------
__global__ void k_edge_max2(const int* __restrict__ src, const int* __restrict__ dst, int E) {
    int e = blockIdx.x * blockDim.x + threadIdx.x;
    if (e >= E) return;
    int s = src[e], d = dst[e];
    float v = leaky(g_el2[s] + g_er2[d]);
    atomicMaxF(&g_m2[d], v);
}

// ---------------- layer 2 fused exp + sum + aggregate -----------------------
// 16 lanes per edge (2 edges per warp)
__global__ void k_edge_agg2(const int* __restrict__ src, const int* __restrict__ dst, int E) {
    int gid = blockIdx.x * blockDim.x + threadIdx.x;
    int e = gid >> 4;
    if (e >= E) return;
    int lane = threadIdx.x & 31;
    int sub = lane & 15;
    int s = src[e], d = dst[e];
    float ex = 0.0f;
    if (sub == 0) {
        float v = leaky(g_el2[s] + g_er2[d]);
        ex = __expf(v - g_m2[d]);
        atomicAdd(&g_s2[d], ex);
    }
    ex = __shfl_sync(0xFFFFFFFFu, ex, lane & 16);
    atomicAdd(&g_rst2[d * 16 + sub], ex * g_feat2[s * 16 + sub]);
}

// ---------------- finalize: normalize + log_softmax -------------------------
__global__ void k_out(const float* __restrict__ b2, float* __restrict__ out, int N) {
    int gid = blockIdx.x * blockDim.x + threadIdx.x;
    int n = gid >> 5;
    if (n >= N) return;
    int lane = threadIdx.x & 31;
    float val;
    if (lane < 16) {
        float s = g_s2[n];
        val = ((s > 0.0f) ? g_rst2[n * 16 + lane] / s : 0.0f) + b2[lane];
    } else {
        val = -CUDART_INF_F;
    }
    float m = val;
#pragma unroll
    for (int o = 16; o; o >>= 1) m = fmaxf(m, __shfl_xor_sync(0xFFFFFFFFu, m, o));
    float ev = (lane < 16) ? __expf(val - m) : 0.0f;
    float ssum = ev;
#pragma unroll
    for (int o = 16; o; o >>= 1) ssum += __shfl_xor_sync(0xFFFFFFFFu, ssum, o);
    if (lane < 16) out[n * 16 + lane] = val - m - logf(ssum);
}

// ---------------- launcher ---------------------------------------------------
extern "C" void kernel_launch(void* const* d_in, const int* in_sizes, int n_in,
                              void* d_out, int out_size) {
    const float* features = (const float*)d_in[0];
    const int*   src      = (const int*)  d_in[1];
    const int*   dst      = (const int*)  d_in[2];
    const float* W1       = (const float*)d_in[3];
    const float* al1      = (const float*)d_in[4];
    const float* ar1      = (const float*)d_in[5];
    const float* b1       = (const float*)d_in[6];
    const float* W2       = (const float*)d_in[7];
    const float* al2      = (const float*)d_in[8];
    const float* ar2      = (const float*)d_in[9];
    const float* b2       = (const float*)d_in[10];
    float* out = (float*)d_out;

    int N = in_sizes[0] / 128;
    int E = in_sizes[1];

    k_init<<<(N * 128 + 255) / 256, 256>>>(N);
    k_gemm1<<<N, 128>>>(features, W1, al1, ar1);
    k_edge_max1<<<(E * 4 + 255) / 256, 256>>>(src, dst, E);
    k_edge_agg1<<<(E * 32 + 255) / 256, 256>>>(src, dst, E);
    k_node1<<<(N * 32 + 255) / 256, 256>>>(b1, N);
    k_gemm2<<<(N * 32 + 255) / 256, 256>>>(W2, al2, ar2, N);
    k_edge_max2<<<(E + 255) / 256, 256>>>(src, dst, E);
    k_edge_agg2<<<(E * 16 + 255) / 256, 256>>>(src, dst, E);
    k_out<<<(N * 32 + 255) / 256, 256>>>(b2, out, N);
}

// round 3
// speedup vs baseline: 1.9068x; 1.9068x over previous
#include <cuda_runtime.h>
#include <math_constants.h>

#define NN 50000
#define EE 1600000

// ---------------- scratch (device globals) ----------------------------------
__device__ __align__(16) float g_feat1[NN * 128];
__device__ __align__(16) float g_el1  [NN * 4];
__device__ __align__(16) float g_er1  [NN * 4];
__device__ __align__(16) float g_x1   [NN * 32];
__device__ __align__(16) float g_feat2[NN * 16];
__device__ float g_el2[NN];
__device__ float g_er2[NN];
__device__ int   g_deg[NN];
__device__ int   g_cur[NN];
__device__ int   g_off[NN + 1];
__device__ int   g_csr[EE];

__device__ __forceinline__ float leaky(float v) { return v > 0.0f ? v : 0.2f * v; }

__device__ __forceinline__ unsigned long long pack2(float x, float y) {
    unsigned long long r;
    asm("mov.b64 %0, {%1,%2};" : "=l"(r) : "f"(x), "f"(y));
    return r;
}
__device__ __forceinline__ void unpack2(unsigned long long v, float& x, float& y) {
    asm("mov.b64 {%0,%1}, %2;" : "=f"(x), "=f"(y) : "l"(v));
}
__device__ __forceinline__ unsigned long long fma2(unsigned long long a, unsigned long long b,
                                                   unsigned long long c) {
    unsigned long long d;
    asm("fma.rn.f32x2 %0, %1, %2, %3;" : "=l"(d) : "l"(a), "l"(b), "l"(c));
    return d;
}

// ---------------- CSR build --------------------------------------------------
__global__ void k_zero(int N) {
    int i = blockIdx.x * blockDim.x + threadIdx.x;
    if (i < N) { g_deg[i] = 0; g_cur[i] = 0; }
}

__global__ void k_hist(const int* __restrict__ dst, int E) {
    int e = blockIdx.x * blockDim.x + threadIdx.x;
    if (e < E) atomicAdd(&g_deg[dst[e]], 1);
}

// single-block exclusive scan of g_deg -> g_off (g_off[N] = E)
__global__ void k_scan(int N) {
    __shared__ int sm[1024];
    __shared__ int carry_s;
    int t = threadIdx.x;
    if (t == 0) carry_s = 0;
    __syncthreads();
    for (int base = 0; base < N; base += 1024) {
        int i = base + t;
        int v = (i < N) ? g_deg[i] : 0;
        sm[t] = v;
        __syncthreads();
        for (int o = 1; o < 1024; o <<= 1) {
            int add = (t >= o) ? sm[t - o] : 0;
            __syncthreads();
            sm[t] += add;
            __syncthreads();
        }
        if (i < N) g_off[i] = carry_s + sm[t] - v;
        __syncthreads();
        if (t == 1023) carry_s += sm[1023];
        __syncthreads();
    }
    if (t == 0) g_off[N] = carry_s;
}

__global__ void k_scatter(const int* __restrict__ src, const int* __restrict__ dst, int E) {
    int e = blockIdx.x * blockDim.x + threadIdx.x;
    if (e >= E) return;
    int d = dst[e];
    int pos = g_off[d] + atomicAdd(&g_cur[d], 1);
    g_csr[pos] = src[e];
}

// ---------------- layer 1 GEMM: 8 nodes/block, packed f32x2 ------------------
__global__ void k_gemm1(const float* __restrict__ x, const float* __restrict__ W, int N) {
    __shared__ __align__(16) float xs[128 * 8];  // [k*8 + nt]
    int t = threadIdx.x;
    int n0 = blockIdx.x * 8;
    for (int j = 0; j < 8; j++) {
        int n = n0 + j;
        xs[t * 8 + j] = (n < N) ? x[n * 128 + t] : 0.0f;
    }
    __syncthreads();
    unsigned long long acc0 = 0, acc1 = 0, acc2 = 0, acc3 = 0;
#pragma unroll 4
    for (int k = 0; k < 128; k++) {
        float w = W[k * 128 + t];
        unsigned long long wd = pack2(w, w);
        const unsigned long long* xp = (const unsigned long long*)&xs[k * 8];
        acc0 = fma2(xp[0], wd, acc0);
        acc1 = fma2(xp[1], wd, acc1);
        acc2 = fma2(xp[2], wd, acc2);
        acc3 = fma2(xp[3], wd, acc3);
    }
    float f0, f1;
    unpack2(acc0, f0, f1);
    if (n0 + 0 < N) g_feat1[(n0 + 0) * 128 + t] = f0;
    if (n0 + 1 < N) g_feat1[(n0 + 1) * 128 + t] = f1;
    unpack2(acc1, f0, f1);
    if (n0 + 2 < N) g_feat1[(n0 + 2) * 128 + t] = f0;
    if (n0 + 3 < N) g_feat1[(n0 + 3) * 128 + t] = f1;
    unpack2(acc2, f0, f1);
    if (n0 + 4 < N) g_feat1[(n0 + 4) * 128 + t] = f0;
    if (n0 + 5 < N) g_feat1[(n0 + 5) * 128 + t] = f1;
    unpack2(acc3, f0, f1);
    if (n0 + 6 < N) g_feat1[(n0 + 6) * 128 + t] = f0;
    if (n0 + 7 < N) g_feat1[(n0 + 7) * 128 + t] = f1;
}

// ---------------- layer 1 el/er: warp per node -------------------------------
__global__ void k_elr1(const float* __restrict__ al, const float* __restrict__ ar, int N) {
    int gid = blockIdx.x * blockDim.x + threadIdx.x;
    int n = gid >> 5;
    if (n >= N) return;
    int lane = threadIdx.x & 31;
    float4 f = *(const float4*)&g_feat1[n * 128 + lane * 4];
    float4 a = *(const float4*)&al[lane * 4];
    float4 r = *(const float4*)&ar[lane * 4];
    float pl = f.x * a.x + f.y * a.y + f.z * a.z + f.w * a.w;
    float pr = f.x * r.x + f.y * r.y + f.z * r.z + f.w * r.w;
#pragma unroll
    for (int o = 1; o < 8; o <<= 1) {
        pl += __shfl_xor_sync(0xFFFFFFFFu, pl, o);
        pr += __shfl_xor_sync(0xFFFFFFFFu, pr, o);
    }
    if ((lane & 7) == 0) {
        int h = lane >> 3;
        g_el1[n * 4 + h] = pl;
        g_er1[n * 4 + h] = pr;
    }
}

// ---------------- layer 1: fused softmax + aggregate + finalize --------------
// warp per destination node; no atomics
__global__ void k_agg1(const float* __restrict__ b1, int N) {
    __shared__ __align__(16) float s_ex[8][128];
    __shared__ int s_s[8][32];
    int wi = threadIdx.x >> 5;
    int lane = threadIdx.x & 31;
    int n = blockIdx.x * 8 + wi;
    if (n >= N) return;
    int beg = g_off[n], end = g_off[n + 1];
    float4 er = *(const float4*)&g_er1[n * 4];

    // pass 1: per-head max over incoming edges
    float m0 = -CUDART_INF_F, m1 = -CUDART_INF_F, m2 = -CUDART_INF_F, m3 = -CUDART_INF_F;
    for (int j = beg + lane; j < end; j += 32) {
        int s = g_csr[j];
        float4 el = *(const float4*)&g_el1[s * 4];
        m0 = fmaxf(m0, leaky(el.x + er.x));
        m1 = fmaxf(m1, leaky(el.y + er.y));
        m2 = fmaxf(m2, leaky(el.z + er.z));
        m3 = fmaxf(m3, leaky(el.w + er.w));
    }
#pragma unroll
    for (int o = 16; o; o >>= 1) {
        m0 = fmaxf(m0, __shfl_xor_sync(0xFFFFFFFFu, m0, o));
        m1 = fmaxf(m1, __shfl_xor_sync(0xFFFFFFFFu, m1, o));
        m2 = fmaxf(m2, __shfl_xor_sync(0xFFFFFFFFu, m2, o));
        m3 = fmaxf(m3, __shfl_xor_sync(0xFFFFFFFFu, m3, o));
    }

    // pass 2: exp + sum + weighted feature accumulation (chunks of 32 edges)
    int h = lane >> 3;  // head of this lane's 4 dims
    float4 acc = make_float4(0.f, 0.f, 0.f, 0.f);
    float sm0 = 0.f, sm1 = 0.f, sm2 = 0.f, sm3 = 0.f;
    for (int base = beg; base < end; base += 32) {
        int valid = min(32, end - base);
        if (lane < valid) {
            int s = g_csr[base + lane];
            float4 el = *(const float4*)&g_el1[s * 4];
            float e0 = __expf(leaky(el.x + er.x) - m0);
            float e1 = __expf(leaky(el.y + er.y) - m1);
            float e2 = __expf(leaky(el.z + er.z) - m2);
            float e3 = __expf(leaky(el.w + er.w) - m3);
            sm0 += e0; sm1 += e1; sm2 += e2; sm3 += e3;
            s_s[wi][lane] = s;
            *(float4*)&s_ex[wi][lane * 4] = make_float4(e0, e1, e2, e3);
        }
        __syncwarp();
        for (int j = 0; j < valid; j++) {
            int sj = s_s[wi][j];
            float ex = s_ex[wi][j * 4 + h];
            float4 f = *(const float4*)&g_feat1[sj * 128 + lane * 4];
            acc.x = fmaf(ex, f.x, acc.x);
            acc.y = fmaf(ex, f.y, acc.y);
            acc.z = fmaf(ex, f.z, acc.z);
            acc.w = fmaf(ex, f.w, acc.w);
        }
        __syncwarp();
    }
#pragma unroll
    for (int o = 16; o; o >>= 1) {
        sm0 += __shfl_xor_sync(0xFFFFFFFFu, sm0, o);
        sm1 += __shfl_xor_sync(0xFFFFFFFFu, sm1, o);
        sm2 += __shfl_xor_sync(0xFFFFFFFFu, sm2, o);
        sm3 += __shfl_xor_sync(0xFFFFFFFFu, sm3, o);
    }
    float ssum = (h == 0) ? sm0 : (h == 1) ? sm1 : (h == 2) ? sm2 : sm3;
    float inv = (ssum > 0.f) ? __frcp_rn(ssum) : 0.f;
    // normalize + bias + relu
    float v0 = fmaxf(acc.x * inv + b1[lane * 4 + 0], 0.f);
    float v1 = fmaxf(acc.y * inv + b1[lane * 4 + 1], 0.f);
    float v2 = fmaxf(acc.z * inv + b1[lane * 4 + 2], 0.f);
    float v3 = fmaxf(acc.w * inv + b1[lane * 4 + 3], 0.f);
    // mean over heads: lanes differing in bits 3,4 share the same hid group
#pragma unroll
    for (int o = 8; o <= 16; o <<= 1) {
        v0 += __shfl_xor_sync(0xFFFFFFFFu, v0, o);
        v1 += __shfl_xor_sync(0xFFFFFFFFu, v1, o);
        v2 += __shfl_xor_sync(0xFFFFFFFFu, v2, o);
        v3 += __shfl_xor_sync(0xFFFFFFFFu, v3, o);
    }
    if (lane < 8) {
        *(float4*)&g_x1[n * 32 + lane * 4] =
            make_float4(v0 * 0.25f, v1 * 0.25f, v2 * 0.25f, v3 * 0.25f);
    }
}

// ---------------- layer 2 GEMM + el2/er2 (warp per node) ---------------------
__global__ void k_gemm2(const float* __restrict__ W2, const float* __restrict__ al2,
                        const float* __restrict__ ar2, int N) {
    int gid = blockIdx.x * blockDim.x + threadIdx.x;
    int n = gid >> 5;
    int lane = threadIdx.x & 31;
    if (n >= N) return;
    float xv = g_x1[n * 32 + lane];
    int t = lane & 15;
    float acc = 0.0f;
#pragma unroll
    for (int k = 0; k < 32; k++)
        acc = fmaf(__shfl_sync(0xFFFFFFFFu, xv, k), W2[k * 16 + t], acc);
    if (lane < 16) g_feat2[n * 16 + t] = acc;
    float pl = (lane < 16) ? acc * al2[t] : 0.0f;
    float pr = (lane < 16) ? acc * ar2[t] : 0.0f;
#pragma unroll
    for (int o = 16; o; o >>= 1) {
        pl += __shfl_xor_sync(0xFFFFFFFFu, pl, o);
        pr += __shfl_xor_sync(0xFFFFFFFFu, pr, o);
    }
    if (lane == 0) { g_el2[n] = pl; g_er2[n] = pr; }
}

// ---------------- layer 2: fused softmax + aggregate + log_softmax ----------
// warp per node; lanes split into two halves of 16 dims
__global__ void k_agg2(const float* __restrict__ b2, float* __restrict__ out, int N) {
    __shared__ float s_ex[8][32];
    __shared__ int s_s[8][32];
    int wi = threadIdx.x >> 5;
    int lane = threadIdx.x & 31;
    int n = blockIdx.x * 8 + wi;
    if (n >= N) return;
    int beg = g_off[n], end = g_off[n + 1];
    float ern = g_er2[n];

    float m = -CUDART_INF_F;
    for (int j = beg + lane; j < end; j += 32)
        m = fmaxf(m, leaky(g_el2[g_csr[j]] + ern));
#pragma unroll
    for (int o = 16; o; o >>= 1)
        m = fmaxf(m, __shfl_xor_sync(0xFFFFFFFFu, m, o));

    int dim = lane & 15;
    int half = lane >> 4;
    float acc = 0.f, psum = 0.f;
    for (int base = beg; base < end; base += 32) {
        int valid = min(32, end - base);
        if (lane < valid) {
            int s = g_csr[base + lane];
            float e = __expf(leaky(g_el2[s] + ern) - m);
            psum += e;
            s_s[wi][lane] = s;
            s_ex[wi][lane] = e;
        }
        __syncwarp();
        for (int j = half; j < valid; j += 2)
            acc = fmaf(s_ex[wi][j], g_feat2[s_s[wi][j] * 16 + dim], acc);
        __syncwarp();
    }
    acc += __shfl_xor_sync(0xFFFFFFFFu, acc, 16);
#pragma unroll
    for (int o = 16; o; o >>= 1)
        psum += __shfl_xor_sync(0xFFFFFFFFu, psum, o);
    float inv = (psum > 0.f) ? __frcp_rn(psum) : 0.f;
    float val = acc * inv + b2[dim];

    // log_softmax over 16 dims (halves are duplicates; xor<=8 stays in group)
    float mm = val;
#pragma unroll
    for (int o = 8; o; o >>= 1)
        mm = fmaxf(mm, __shfl_xor_sync(0xFFFFFFFFu, mm, o));
    float ev = __expf(val - mm);
    float es = ev;
#pragma unroll
    for (int o = 8; o; o >>= 1)
        es += __shfl_xor_sync(0xFFFFFFFFu, es, o);
    if (lane < 16) out[n * 16 + dim] = val - mm - logf(es);
}

// ---------------- launcher ---------------------------------------------------
extern "C" void kernel_launch(void* const* d_in, const int* in_sizes, int n_in,
                              void* d_out, int out_size) {
    const float* features = (const float*)d_in[0];
    const int*   src      = (const int*)  d_in[1];
    const int*   dst      = (const int*)  d_in[2];
    const float* W1       = (const float*)d_in[3];
    const float* al1      = (const float*)d_in[4];
    const float* ar1      = (const float*)d_in[5];
    const float* b1       = (const float*)d_in[6];
    const float* W2       = (const float*)d_in[7];
    const float* al2      = (const float*)d_in[8];
    const float* ar2      = (const float*)d_in[9];
    const float* b2       = (const float*)d_in[10];
    float* out = (float*)d_out;

    int N = in_sizes[0] / 128;
    int E = in_sizes[1];

    k_zero<<<(N + 255) / 256, 256>>>(N);
    k_hist<<<(E + 255) / 256, 256>>>(dst, E);
    k_scan<<<1, 1024>>>(N);
    k_scatter<<<(E + 255) / 256, 256>>>(src, dst, E);
    k_gemm1<<<(N + 7) / 8, 128>>>(features, W1, N);
    k_elr1<<<(N * 32 + 255) / 256, 256>>>(al1, ar1, N);
    k_agg1<<<(N + 7) / 8, 256>>>(b1, N);
    k_gemm2<<<(N * 32 + 255) / 256, 256>>>(W2, al2, ar2, N);
    k_agg2<<<(N + 7) / 8, 256>>>(b2, out, N);
}

// round 5
// speedup vs baseline: 2.7121x; 1.4223x over previous
#include <cuda_runtime.h>
#include <cuda_fp16.h>
#include <math_constants.h>

#define NN 50000
#define EE 1600000

// ---------------- scratch (device globals) ----------------------------------
__device__ __align__(16) __half g_feat1h[NN * 128];
__device__ __align__(16) float g_el1  [NN * 4];
__device__ __align__(16) float g_er1  [NN * 4];
__device__ __align__(16) float g_x1   [NN * 32];
__device__ __align__(16) float g_feat2[NN * 16];
__device__ float g_el2[NN];
__device__ float g_er2[NN];
__device__ int   g_deg[NN];
__device__ int   g_off[NN + 1];
__device__ int   g_csr[EE];
__device__ int   g_rank[EE];
__device__ int   g_bsum[64];
__device__ int   g_boff[64];

__device__ __forceinline__ float leaky(float v) { return v > 0.0f ? v : 0.2f * v; }

__device__ __forceinline__ unsigned long long pack2(float x, float y) {
    unsigned long long r;
    asm("mov.b64 %0, {%1,%2};" : "=l"(r) : "f"(x), "f"(y));
    return r;
}
__device__ __forceinline__ void unpack2(unsigned long long v, float& x, float& y) {
    asm("mov.b64 {%0,%1}, %2;" : "=f"(x), "=f"(y) : "l"(v));
}
__device__ __forceinline__ unsigned long long fma2(unsigned long long a, unsigned long long b,
                                                   unsigned long long c) {
    unsigned long long d;
    asm("fma.rn.f32x2 %0, %1, %2, %3;" : "=l"(d) : "l"(a), "l"(b), "l"(c));
    return d;
}

// ---------------- CSR build --------------------------------------------------
__global__ void k_zero(int N) {
    int i = blockIdx.x * blockDim.x + threadIdx.x;
    if (i < N) g_deg[i] = 0;
}

// histogram; the atomic's return value IS the within-segment rank
__global__ void k_hist(const int* __restrict__ dst, int E) {
    int e = blockIdx.x * blockDim.x + threadIdx.x;
    if (e < E) g_rank[e] = atomicAdd(&g_deg[dst[e]], 1);
}

// phase A: per-1024-block exclusive scan (pre-carry) + block sums
__global__ void k_scanA(int N) {
    __shared__ int sm[1024];
    int t = threadIdx.x;
    int i = blockIdx.x * 1024 + t;
    int v = (i < N) ? g_deg[i] : 0;
    sm[t] = v;
    __syncthreads();
#pragma unroll
    for (int o = 1; o < 1024; o <<= 1) {
        int a = (t >= o) ? sm[t - o] : 0;
        __syncthreads();
        sm[t] += a;
        __syncthreads();
    }
    if (i < N) g_off[i] = sm[t] - v;
    if (t == 1023) g_bsum[blockIdx.x] = sm[1023];
}

// phase B: scan the (<=64) block sums; write total to g_off[N]
__global__ void k_scanB(int NB, int N) {
    __shared__ int sm[64];
    int t = threadIdx.x;  // 64 threads
    int v = (t < NB) ? g_bsum[t] : 0;
    sm[t] = v;
    __syncthreads();
#pragma unroll
    for (int o = 1; o < 64; o <<= 1) {
        int a = (t >= o) ? sm[t - o] : 0;
        __syncthreads();
        sm[t] += a;
        __syncthreads();
    }
    g_boff[t] = sm[t] - v;
    if (t == 63) g_off[N] = sm[63];
}

// phase C: add block carry
__global__ void k_scanC(int N) {
    int i = blockIdx.x * 1024 + threadIdx.x;
    if (i < N) g_off[i] += g_boff[blockIdx.x];
}

// scatter: no atomics (rank precomputed)
__global__ void k_scatter(const int* __restrict__ src, const int* __restrict__ dst, int E) {
    int e = blockIdx.x * blockDim.x + threadIdx.x;
    if (e >= E) return;
    g_csr[g_off[dst[e]] + g_rank[e]] = src[e];
}

// ---------------- layer 1 GEMM: 8 nodes/block, packed f32x2, fp16 out --------
__global__ void k_gemm1(const float* __restrict__ x, const float* __restrict__ W, int N) {
    __shared__ __align__(16) float xs[128 * 8];  // [k*8 + j]
    int t = threadIdx.x;
    int n0 = blockIdx.x * 8;
    for (int j = 0; j < 8; j++) {
        int n = n0 + j;
        xs[t * 8 + j] = (n < N) ? x[n * 128 + t] : 0.0f;
    }
    __syncthreads();
    unsigned long long acc0 = 0, acc1 = 0, acc2 = 0, acc3 = 0;
#pragma unroll 4
    for (int k = 0; k < 128; k++) {
        float w = W[k * 128 + t];
        unsigned long long wd = pack2(w, w);
        const unsigned long long* xp = (const unsigned long long*)&xs[k * 8];
        acc0 = fma2(xp[0], wd, acc0);
        acc1 = fma2(xp[1], wd, acc1);
        acc2 = fma2(xp[2], wd, acc2);
        acc3 = fma2(xp[3], wd, acc3);
    }
    float f0, f1;
    unpack2(acc0, f0, f1);
    if (n0 + 0 < N) g_feat1h[(n0 + 0) * 128 + t] = __float2half_rn(f0);
    if (n0 + 1 < N) g_feat1h[(n0 + 1) * 128 + t] = __float2half_rn(f1);
    unpack2(acc1, f0, f1);
    if (n0 + 2 < N) g_feat1h[(n0 + 2) * 128 + t] = __float2half_rn(f0);
    if (n0 + 3 < N) g_feat1h[(n0 + 3) * 128 + t] = __float2half_rn(f1);
    unpack2(acc2, f0, f1);
    if (n0 + 4 < N) g_feat1h[(n0 + 4) * 128 + t] = __float2half_rn(f0);
    if (n0 + 5 < N) g_feat1h[(n0 + 5) * 128 + t] = __float2half_rn(f1);
    unpack2(acc3, f0, f1);
    if (n0 + 6 < N) g_feat1h[(n0 + 6) * 128 + t] = __float2half_rn(f0);
    if (n0 + 7 < N) g_feat1h[(n0 + 7) * 128 + t] = __float2half_rn(f1);
}

// ---------------- layer 1 el/er: warp per node -------------------------------
__global__ void k_elr1(const float* __restrict__ al, const float* __restrict__ ar, int N) {
    int gid = blockIdx.x * blockDim.x + threadIdx.x;
    int n = gid >> 5;
    if (n >= N) return;
    int lane = threadIdx.x & 31;
    uint2 u = *(const uint2*)&g_feat1h[n * 128 + lane * 4];
    float2 f01 = __half22float2(*(const __half2*)&u.x);
    float2 f23 = __half22float2(*(const __half2*)&u.y);
    float4 a = *(const float4*)&al[lane * 4];
    float4 r = *(const float4*)&ar[lane * 4];
    float pl = f01.x * a.x + f01.y * a.y + f23.x * a.z + f23.y * a.w;
    float pr = f01.x * r.x + f01.y * r.y + f23.x * r.z + f23.y * r.w;
#pragma unroll
    for (int o = 1; o < 8; o <<= 1) {
        pl += __shfl_xor_sync(0xFFFFFFFFu, pl, o);
        pr += __shfl_xor_sync(0xFFFFFFFFu, pr, o);
    }
    if ((lane & 7) == 0) {
        int h = lane >> 3;
        g_el1[n * 4 + h] = pl;
        g_er1[n * 4 + h] = pr;
    }
}

// ---------------- layer 1: fused softmax + aggregate + finalize --------------
__global__ void k_agg1(const float* __restrict__ b1, int N) {
    __shared__ __align__(16) float s_ex[8][128];
    __shared__ int s_s[8][32];
    int wi = threadIdx.x >> 5;
    int lane = threadIdx.x & 31;
    int n = blockIdx.x * 8 + wi;
    if (n >= N) return;
    int beg = g_off[n], end = g_off[n + 1];
    float4 er = *(const float4*)&g_er1[n * 4];

    // pass 1: per-head max over incoming edges
    float m0 = -CUDART_INF_F, m1 = -CUDART_INF_F, m2 = -CUDART_INF_F, m3 = -CUDART_INF_F;
    for (int j = beg + lane; j < end; j += 32) {
        int s = g_csr[j];
        float4 el = *(const float4*)&g_el1[s * 4];
        m0 = fmaxf(m0, leaky(el.x + er.x));
        m1 = fmaxf(m1, leaky(el.y + er.y));
        m2 = fmaxf(m2, leaky(el.z + er.z));
        m3 = fmaxf(m3, leaky(el.w + er.w));
    }
#pragma unroll
    for (int o = 16; o; o >>= 1) {
        m0 = fmaxf(m0, __shfl_xor_sync(0xFFFFFFFFu, m0, o));
        m1 = fmaxf(m1, __shfl_xor_sync(0xFFFFFFFFu, m1, o));
        m2 = fmaxf(m2, __shfl_xor_sync(0xFFFFFFFFu, m2, o));
        m3 = fmaxf(m3, __shfl_xor_sync(0xFFFFFFFFu, m3, o));
    }

    // pass 2: exp + sum + weighted feature accumulation (fp16 features)
    int h = lane >> 3;
    float4 acc = make_float4(0.f, 0.f, 0.f, 0.f);
    float sm0 = 0.f, sm1 = 0.f, sm2 = 0.f, sm3 = 0.f;
    for (int base = beg; base < end; base += 32) {
        int valid = min(32, end - base);
        if (lane < valid) {
            int s = g_csr[base + lane];
            float4 el = *(const float4*)&g_el1[s * 4];
            float e0 = __expf(leaky(el.x + er.x) - m0);
            float e1 = __expf(leaky(el.y + er.y) - m1);
            float e2 = __expf(leaky(el.z + er.z) - m2);
            float e3 = __expf(leaky(el.w + er.w) - m3);
            sm0 += e0; sm1 += e1; sm2 += e2; sm3 += e3;
            s_s[wi][lane] = s;
            *(float4*)&s_ex[wi][lane * 4] = make_float4(e0, e1, e2, e3);
        }
        __syncwarp();
        for (int j = 0; j < valid; j++) {
            int sj = s_s[wi][j];
            float ex = s_ex[wi][j * 4 + h];
            uint2 u = *(const uint2*)&g_feat1h[sj * 128 + lane * 4];
            float2 f01 = __half22float2(*(const __half2*)&u.x);
            float2 f23 = __half22float2(*(const __half2*)&u.y);
            acc.x = fmaf(ex, f01.x, acc.x);
            acc.y = fmaf(ex, f01.y, acc.y);
            acc.z = fmaf(ex, f23.x, acc.z);
            acc.w = fmaf(ex, f23.y, acc.w);
        }
        __syncwarp();
    }
#pragma unroll
    for (int o = 16; o; o >>= 1) {
        sm0 += __shfl_xor_sync(0xFFFFFFFFu, sm0, o);
        sm1 += __shfl_xor_sync(0xFFFFFFFFu, sm1, o);
        sm2 += __shfl_xor_sync(0xFFFFFFFFu, sm2, o);
        sm3 += __shfl_xor_sync(0xFFFFFFFFu, sm3, o);
    }
    float ssum = (h == 0) ? sm0 : (h == 1) ? sm1 : (h == 2) ? sm2 : sm3;
    float inv = (ssum > 0.f) ? __frcp_rn(ssum) : 0.f;
    float v0 = fmaxf(acc.x * inv + b1[lane * 4 + 0], 0.f);
    float v1 = fmaxf(acc.y * inv + b1[lane * 4 + 1], 0.f);
    float v2 = fmaxf(acc.z * inv + b1[lane * 4 + 2], 0.f);
    float v3 = fmaxf(acc.w * inv + b1[lane * 4 + 3], 0.f);
#pragma unroll
    for (int o = 8; o <= 16; o <<= 1) {
        v0 += __shfl_xor_sync(0xFFFFFFFFu, v0, o);
        v1 += __shfl_xor_sync(0xFFFFFFFFu, v1, o);
        v2 += __shfl_xor_sync(0xFFFFFFFFu, v2, o);
        v3 += __shfl_xor_sync(0xFFFFFFFFu, v3, o);
    }
    if (lane < 8) {
        *(float4*)&g_x1[n * 32 + lane * 4] =
            make_float4(v0 * 0.25f, v1 * 0.25f, v2 * 0.25f, v3 * 0.25f);
    }
}

// ---------------- layer 2 GEMM + el2/er2 (warp per node) ---------------------
__global__ void k_gemm2(const float* __restrict__ W2, const float* __restrict__ al2,
                        const float* __restrict__ ar2, int N) {
    int gid = blockIdx.x * blockDim.x + threadIdx.x;
    int n = gid >> 5;
    int lane = threadIdx.x & 31;
    if (n >= N) return;
    float xv = g_x1[n * 32 + lane];
    int t = lane & 15;
    float acc = 0.0f;
#pragma unroll
    for (int k = 0; k < 32; k++)
        acc = fmaf(__shfl_sync(0xFFFFFFFFu, xv, k), W2[k * 16 + t], acc);
    if (lane < 16) g_feat2[n * 16 + t] = acc;
    float pl = (lane < 16) ? acc * al2[t] : 0.0f;
    float pr = (lane < 16) ? acc * ar2[t] : 0.0f;
#pragma unroll
    for (int o = 16; o; o >>= 1) {
        pl += __shfl_xor_sync(0xFFFFFFFFu, pl, o);
        pr += __shfl_xor_sync(0xFFFFFFFFu, pr, o);
    }
    if (lane == 0) { g_el2[n] = pl; g_er2[n] = pr; }
}

// ---------------- layer 2: fused softmax + aggregate + log_softmax ----------
// warp per node; 8 edges in flight (4-lane groups, float4 per lane)
__global__ void k_agg2(const float* __restrict__ b2, float* __restrict__ out, int N) {
    __shared__ float s_ex[8][32];
    __shared__ int s_s[8][32];
    int wi = threadIdx.x >> 5;
    int lane = threadIdx.x & 31;
    int n = blockIdx.x * 8 + wi;
    if (n >= N) return;
    int beg = g_off[n], end = g_off[n + 1];
    float ern = g_er2[n];

    float m = -CUDART_INF_F;
    for (int j = beg + lane; j < end; j += 32)
        m = fmaxf(m, leaky(g_el2[g_csr[j]] + ern));
#pragma unroll
    for (int o = 16; o; o >>= 1)
        m = fmaxf(m, __shfl_xor_sync(0xFFFFFFFFu, m, o));

    int eg = lane >> 2;        // edge group 0..7
    int dg = lane & 3;         // dim group 0..3 (float4)
    float4 acc = make_float4(0.f, 0.f, 0.f, 0.f);
    float psum = 0.f;
    for (int base = beg; base < end; base += 32) {
        int valid = min(32, end - base);
        if (lane < valid) {
            int s = g_csr[base + lane];
            float e = __expf(leaky(g_el2[s] + ern) - m);
            psum += e;
            s_s[wi][lane] = s;
            s_ex[wi][lane] = e;
        }
        __syncwarp();
        for (int j0 = 0; j0 < valid; j0 += 8) {
            int j = j0 + eg;
            if (j < valid) {
                float ex = s_ex[wi][j];
                float4 f = *(const float4*)&g_feat2[s_s[wi][j] * 16 + dg * 4];
                acc.x = fmaf(ex, f.x, acc.x);
                acc.y = fmaf(ex, f.y, acc.y);
                acc.z = fmaf(ex, f.z, acc.z);
                acc.w = fmaf(ex, f.w, acc.w);
            }
        }
        __syncwarp();
    }
    // reduce across edge groups (xor 4,8,16) -> every lane with same dg has full sum
#pragma unroll
    for (int o = 4; o <= 16; o <<= 1) {
        acc.x += __shfl_xor_sync(0xFFFFFFFFu, acc.x, o);
        acc.y += __shfl_xor_sync(0xFFFFFFFFu, acc.y, o);
        acc.z += __shfl_xor_sync(0xFFFFFFFFu, acc.z, o);
        acc.w += __shfl_xor_sync(0xFFFFFFFFu, acc.w, o);
    }
#pragma unroll
    for (int o = 16; o; o >>= 1)
        psum += __shfl_xor_sync(0xFFFFFFFFu, psum, o);
    float inv = (psum > 0.f) ? __frcp_rn(psum) : 0.f;
    float4 bb = *(const float4*)&b2[dg * 4];
    float4 val = make_float4(acc.x * inv + bb.x, acc.y * inv + bb.y,
                             acc.z * inv + bb.z, acc.w * inv + bb.w);

    // log_softmax over 16 dims: per-lane max/sum over 4 comps, then xor 1,2
    float mm = fmaxf(fmaxf(val.x, val.y), fmaxf(val.z, val.w));
#pragma unroll
    for (int o = 1; o <= 2; o <<= 1)
        mm = fmaxf(mm, __shfl_xor_sync(0xFFFFFFFFu, mm, o));
    float es = __expf(val.x - mm) + __expf(val.y - mm) +
               __expf(val.z - mm) + __expf(val.w - mm);
#pragma unroll
    for (int o = 1; o <= 2; o <<= 1)
        es += __shfl_xor_sync(0xFFFFFFFFu, es, o);
    float lse = mm + logf(es);
    if (lane < 4) {
        *(float4*)&out[n * 16 + dg * 4] =
            make_float4(val.x - lse, val.y - lse, val.z - lse, val.w - lse);
    }
}

// ---------------- launcher ---------------------------------------------------
extern "C" void kernel_launch(void* const* d_in, const int* in_sizes, int n_in,
                              void* d_out, int out_size) {
    const float* features = (const float*)d_in[0];
    const int*   src      = (const int*)  d_in[1];
    const int*   dst      = (const int*)  d_in[2];
    const float* W1       = (const float*)d_in[3];
    const float* al1      = (const float*)d_in[4];
    const float* ar1      = (const float*)d_in[5];
    const float* b1       = (const float*)d_in[6];
    const float* W2       = (const float*)d_in[7];
    const float* al2      = (const float*)d_in[8];
    const float* ar2      = (const float*)d_in[9];
    const float* b2       = (const float*)d_in[10];
    float* out = (float*)d_out;

    int N = in_sizes[0] / 128;
    int E = in_sizes[1];
    int NB = (N + 1023) / 1024;

    k_zero<<<(N + 255) / 256, 256>>>(N);
    k_hist<<<(E + 255) / 256, 256>>>(dst, E);
    k_scanA<<<NB, 1024>>>(N);
    k_scanB<<<1, 64>>>(NB, N);
    k_scanC<<<NB, 1024>>>(N);
    k_scatter<<<(E + 255) / 256, 256>>>(src, dst, E);
    k_gemm1<<<(N + 7) / 8, 128>>>(features, W1, N);
    k_elr1<<<(N * 32 + 255) / 256, 256>>>(al1, ar1, N);
    k_agg1<<<(N + 7) / 8, 256>>>(b1, N);
    k_gemm2<<<(N * 32 + 255) / 256, 256>>>(W2, al2, ar2, N);
    k_agg2<<<(N + 7) / 8, 256>>>(b2, out, N);
}

// round 6
// speedup vs baseline: 3.1836x; 1.1739x over previous
#include <cuda_runtime.h>
#include <cuda_fp16.h>
#include <math_constants.h>

#define NN 50000
#define EE 1600000

// ---------------- scratch (device globals) ----------------------------------
__device__ __align__(16) __half g_feat1h[NN * 128];
__device__ __align__(16) __half g_W1t[128 * 128];   // W1 transposed [n][k], fp16
__device__ __align__(16) float g_el1  [NN * 4];
__device__ __align__(16) float g_er1  [NN * 4];
__device__ __align__(16) float g_x1   [NN * 32];
__device__ __align__(16) float g_feat2[NN * 16];
__device__ float g_el2[NN];
__device__ float g_er2[NN];
__device__ int   g_deg[NN];
__device__ int   g_off[NN + 1];
__device__ int   g_csr[EE];
__device__ int   g_rank[EE];
__device__ int   g_bsum[64];
__device__ int   g_boff[64];

__device__ __forceinline__ float leaky(float v) { return v > 0.0f ? v : 0.2f * v; }

// ---------------- CSR build --------------------------------------------------
__global__ void k_zero(int N) {
    int i = blockIdx.x * blockDim.x + threadIdx.x;
    if (i < N) g_deg[i] = 0;
}

__global__ void k_hist(const int* __restrict__ dst, int E) {
    int e = blockIdx.x * blockDim.x + threadIdx.x;
    if (e < E) g_rank[e] = atomicAdd(&g_deg[dst[e]], 1);
}

__global__ void k_scanA(int N) {
    __shared__ int sm[1024];
    int t = threadIdx.x;
    int i = blockIdx.x * 1024 + t;
    int v = (i < N) ? g_deg[i] : 0;
    sm[t] = v;
    __syncthreads();
#pragma unroll
    for (int o = 1; o < 1024; o <<= 1) {
        int a = (t >= o) ? sm[t - o] : 0;
        __syncthreads();
        sm[t] += a;
        __syncthreads();
    }
    if (i < N) g_off[i] = sm[t] - v;
    if (t == 1023) g_bsum[blockIdx.x] = sm[1023];
}

__global__ void k_scanB(int NB, int N) {
    __shared__ int sm[64];
    int t = threadIdx.x;
    int v = (t < NB) ? g_bsum[t] : 0;
    sm[t] = v;
    __syncthreads();
#pragma unroll
    for (int o = 1; o < 64; o <<= 1) {
        int a = (t >= o) ? sm[t - o] : 0;
        __syncthreads();
        sm[t] += a;
        __syncthreads();
    }
    g_boff[t] = sm[t] - v;
    if (t == 63) g_off[N] = sm[63];
}

__global__ void k_scanC(int N) {
    int i = blockIdx.x * 1024 + threadIdx.x;
    if (i < N) g_off[i] += g_boff[blockIdx.x];
}

__global__ void k_scatter(const int* __restrict__ src, const int* __restrict__ dst, int E) {
    int e = blockIdx.x * blockDim.x + threadIdx.x;
    if (e >= E) return;
    g_csr[g_off[dst[e]] + g_rank[e]] = src[e];
}

// ---------------- W1 -> fp16 transposed [n][k] -------------------------------
__global__ void k_cvtW(const float* __restrict__ W1) {
    int n = blockIdx.x;        // 128 blocks
    int k = threadIdx.x;       // 128 threads
    g_W1t[n * 128 + k] = __float2half_rn(W1[k * 128 + n]);
}

// ---------------- layer 1 GEMM via tensor cores (m16n8k16) -------------------
// block: 256 threads (8 warps), 128 M-rows per block, full N=128, K=128
#define AS_STRIDE 136
__global__ void k_gemm1(const float* __restrict__ x, int N) {
    extern __shared__ __align__(16) __half smem[];
    __half* As = smem;                     // [128][136]
    __half* Ws = smem + 128 * AS_STRIDE;   // [128][136]  (W1t: [n][k])
    int t = threadIdx.x;
    int m0 = blockIdx.x * 128;

    // stage W1t (fp16, 128x128) into smem
    {
        int r = t >> 1;
        int c0 = (t & 1) * 64;
        const uint4* srcp = (const uint4*)&g_W1t[r * 128 + c0];
        uint4* dstp = (uint4*)&Ws[r * AS_STRIDE + c0];
#pragma unroll
        for (int i = 0; i < 8; i++) dstp[i] = srcp[i];
    }
    // stage features (fp32 -> fp16) into smem
    {
        int r = t >> 1;
        int c0 = (t & 1) * 64;
        int m = m0 + r;
#pragma unroll
        for (int i = 0; i < 64; i += 4) {
            float4 v = (m < N) ? *(const float4*)&x[m * 128 + c0 + i]
                               : make_float4(0.f, 0.f, 0.f, 0.f);
            __half2 h01 = __floats2half2_rn(v.x, v.y);
            __half2 h23 = __floats2half2_rn(v.z, v.w);
            uint2 pk;
            pk.x = *(unsigned*)&h01;
            pk.y = *(unsigned*)&h23;
            *(uint2*)&As[r * AS_STRIDE + c0 + i] = pk;
        }
    }
    __syncthreads();

    int w = t >> 5, lane = t & 31;
    int g = lane >> 2, tg = lane & 3;
    int mrow = w * 16;

    float acc[16][4];
#pragma unroll
    for (int nt = 0; nt < 16; nt++)
#pragma unroll
        for (int i = 0; i < 4; i++) acc[nt][i] = 0.f;

#pragma unroll
    for (int k0 = 0; k0 < 128; k0 += 16) {
        unsigned ra0 = *(const unsigned*)&As[(mrow + g)     * AS_STRIDE + k0 + tg * 2];
        unsigned ra1 = *(const unsigned*)&As[(mrow + g + 8) * AS_STRIDE + k0 + tg * 2];
        unsigned ra2 = *(const unsigned*)&As[(mrow + g)     * AS_STRIDE + k0 + tg * 2 + 8];
        unsigned ra3 = *(const unsigned*)&As[(mrow + g + 8) * AS_STRIDE + k0 + tg * 2 + 8];
#pragma unroll
        for (int nt = 0; nt < 16; nt++) {
            unsigned rb0 = *(const unsigned*)&Ws[(nt * 8 + g) * AS_STRIDE + k0 + tg * 2];
            unsigned rb1 = *(const unsigned*)&Ws[(nt * 8 + g) * AS_STRIDE + k0 + tg * 2 + 8];
            asm volatile(
                "mma.sync.aligned.m16n8k16.row.col.f32.f16.f16.f32 "
                "{%0,%1,%2,%3}, {%4,%5,%6,%7}, {%8,%9}, {%0,%1,%2,%3};"
                : "+f"(acc[nt][0]), "+f"(acc[nt][1]), "+f"(acc[nt][2]), "+f"(acc[nt][3])
                : "r"(ra0), "r"(ra1), "r"(ra2), "r"(ra3), "r"(rb0), "r"(rb1));
        }
    }

    int m_g = m0 + mrow + g;
    if (m_g < N) {
#pragma unroll
        for (int nt = 0; nt < 16; nt++) {
            __half2 h = __floats2half2_rn(acc[nt][0], acc[nt][1]);
            *(__half2*)&g_feat1h[m_g * 128 + nt * 8 + tg * 2] = h;
        }
    }
    int m_g8 = m_g + 8;
    if (m_g8 < N) {
#pragma unroll
        for (int nt = 0; nt < 16; nt++) {
            __half2 h = __floats2half2_rn(acc[nt][2], acc[nt][3]);
            *(__half2*)&g_feat1h[m_g8 * 128 + nt * 8 + tg * 2] = h;
        }
    }
}

// ---------------- layer 1 el/er: warp per node -------------------------------
__global__ void k_elr1(const float* __restrict__ al, const float* __restrict__ ar, int N) {
    int gid = blockIdx.x * blockDim.x + threadIdx.x;
    int n = gid >> 5;
    if (n >= N) return;
    int lane = threadIdx.x & 31;
    uint2 u = *(const uint2*)&g_feat1h[n * 128 + lane * 4];
    float2 f01 = __half22float2(*(const __half2*)&u.x);
    float2 f23 = __half22float2(*(const __half2*)&u.y);
    float4 a = *(const float4*)&al[lane * 4];
    float4 r = *(const float4*)&ar[lane * 4];
    float pl = f01.x * a.x + f01.y * a.y + f23.x * a.z + f23.y * a.w;
    float pr = f01.x * r.x + f01.y * r.y + f23.x * r.z + f23.y * r.w;
#pragma unroll
    for (int o = 1; o < 8; o <<= 1) {
        pl += __shfl_xor_sync(0xFFFFFFFFu, pl, o);
        pr += __shfl_xor_sync(0xFFFFFFFFu, pr, o);
    }
    if ((lane & 7) == 0) {
        int h = lane >> 3;
        g_el1[n * 4 + h] = pl;
        g_er1[n * 4 + h] = pr;
    }
}

// ---------------- layer 1: fused softmax + aggregate + finalize --------------
// warp per node; 2 edges in flight, 16 lanes x 8 dims (uint4 fp16 loads)
__global__ void k_agg1(const float* __restrict__ b1, int N) {
    __shared__ __align__(16) float s_ex[8][128];
    __shared__ int s_s[8][32];
    int wi = threadIdx.x >> 5;
    int lane = threadIdx.x & 31;
    int n = blockIdx.x * 8 + wi;
    if (n >= N) return;
    int beg = g_off[n], end = g_off[n + 1];
    float4 er = *(const float4*)&g_er1[n * 4];

    // pass 1: per-head max
    float m0 = -CUDART_INF_F, m1 = -CUDART_INF_F, m2 = -CUDART_INF_F, m3 = -CUDART_INF_F;
    for (int j = beg + lane; j < end; j += 32) {
        int s = g_csr[j];
        float4 el = *(const float4*)&g_el1[s * 4];
        m0 = fmaxf(m0, leaky(el.x + er.x));
        m1 = fmaxf(m1, leaky(el.y + er.y));
        m2 = fmaxf(m2, leaky(el.z + er.z));
        m3 = fmaxf(m3, leaky(el.w + er.w));
    }
#pragma unroll
    for (int o = 16; o; o >>= 1) {
        m0 = fmaxf(m0, __shfl_xor_sync(0xFFFFFFFFu, m0, o));
        m1 = fmaxf(m1, __shfl_xor_sync(0xFFFFFFFFu, m1, o));
        m2 = fmaxf(m2, __shfl_xor_sync(0xFFFFFFFFu, m2, o));
        m3 = fmaxf(m3, __shfl_xor_sync(0xFFFFFFFFu, m3, o));
    }

    // pass 2: exp + sum + weighted aggregate
    int e2 = lane >> 4;        // edge parity 0/1
    int lh = lane & 15;        // 8-dim group: dims lh*8..lh*8+7
    int h  = lh >> 2;          // head of this lane's dims
    float acc[8];
#pragma unroll
    for (int i = 0; i < 8; i++) acc[i] = 0.f;
    float sm0 = 0.f, sm1 = 0.f, sm2 = 0.f, sm3 = 0.f;

    for (int base = beg; base < end; base += 32) {
        int valid = min(32, end - base);
        if (lane < valid) {
            int s = g_csr[base + lane];
            float4 el = *(const float4*)&g_el1[s * 4];
            float e0 = __expf(leaky(el.x + er.x) - m0);
            float e1 = __expf(leaky(el.y + er.y) - m1);
            float e2f = __expf(leaky(el.z + er.z) - m2);
            float e3 = __expf(leaky(el.w + er.w) - m3);
            sm0 += e0; sm1 += e1; sm2 += e2f; sm3 += e3;
            s_s[wi][lane] = s;
            *(float4*)&s_ex[wi][lane * 4] = make_float4(e0, e1, e2f, e3);
        }
        __syncwarp();
#pragma unroll 2
        for (int j0 = 0; j0 < valid; j0 += 2) {
            int j = j0 + e2;
            if (j < valid) {
                float ex = s_ex[wi][j * 4 + h];
                int sj = s_s[wi][j];
                uint4 u = *(const uint4*)&g_feat1h[sj * 128 + lh * 8];
                float2 f0 = __half22float2(*(const __half2*)&u.x);
                float2 f1 = __half22float2(*(const __half2*)&u.y);
                float2 f2 = __half22float2(*(const __half2*)&u.z);
                float2 f3 = __half22float2(*(const __half2*)&u.w);
                acc[0] = fmaf(ex, f0.x, acc[0]);
                acc[1] = fmaf(ex, f0.y, acc[1]);
                acc[2] = fmaf(ex, f1.x, acc[2]);
                acc[3] = fmaf(ex, f1.y, acc[3]);
                acc[4] = fmaf(ex, f2.x, acc[4]);
                acc[5] = fmaf(ex, f2.y, acc[5]);
                acc[6] = fmaf(ex, f3.x, acc[6]);
                acc[7] = fmaf(ex, f3.y, acc[7]);
            }
        }
        __syncwarp();
    }
    // combine the two edge-parity halves
#pragma unroll
    for (int i = 0; i < 8; i++) acc[i] += __shfl_xor_sync(0xFFFFFFFFu, acc[i], 16);
    // head sums
#pragma unroll
    for (int o = 16; o; o >>= 1) {
        sm0 += __shfl_xor_sync(0xFFFFFFFFu, sm0, o);
        sm1 += __shfl_xor_sync(0xFFFFFFFFu, sm1, o);
        sm2 += __shfl_xor_sync(0xFFFFFFFFu, sm2, o);
        sm3 += __shfl_xor_sync(0xFFFFFFFFu, sm3, o);
    }
    float ssum = (h == 0) ? sm0 : (h == 1) ? sm1 : (h == 2) ? sm2 : sm3;
    float inv = (ssum > 0.f) ? __frcp_rn(ssum) : 0.f;
    float4 ba = *(const float4*)&b1[lh * 8];
    float4 bb = *(const float4*)&b1[lh * 8 + 4];
    float v[8];
    v[0] = fmaxf(acc[0] * inv + ba.x, 0.f);
    v[1] = fmaxf(acc[1] * inv + ba.y, 0.f);
    v[2] = fmaxf(acc[2] * inv + ba.z, 0.f);
    v[3] = fmaxf(acc[3] * inv + ba.w, 0.f);
    v[4] = fmaxf(acc[4] * inv + bb.x, 0.f);
    v[5] = fmaxf(acc[5] * inv + bb.y, 0.f);
    v[6] = fmaxf(acc[6] * inv + bb.z, 0.f);
    v[7] = fmaxf(acc[7] * inv + bb.w, 0.f);
    // mean over heads: head index = lh bits 2..3 -> xor 4, 8
#pragma unroll
    for (int o = 4; o <= 8; o <<= 1)
#pragma unroll
        for (int i = 0; i < 8; i++) v[i] += __shfl_xor_sync(0xFFFFFFFFu, v[i], o);
    if (lane < 4) {
        *(float4*)&g_x1[n * 32 + lane * 8] =
            make_float4(v[0] * 0.25f, v[1] * 0.25f, v[2] * 0.25f, v[3] * 0.25f);
        *(float4*)&g_x1[n * 32 + lane * 8 + 4] =
            make_float4(v[4] * 0.25f, v[5] * 0.25f, v[6] * 0.25f, v[7] * 0.25f);
    }
}

// ---------------- layer 2 GEMM + el2/er2 (warp per node) ---------------------
__global__ void k_gemm2(const float* __restrict__ W2, const float* __restrict__ al2,
                        const float* __restrict__ ar2, int N) {
    int gid = blockIdx.x * blockDim.x + threadIdx.x;
    int n = gid >> 5;
    int lane = threadIdx.x & 31;
    if (n >= N) return;
    float xv = g_x1[n * 32 + lane];
    int t = lane & 15;
    float acc = 0.0f;
#pragma unroll
    for (int k = 0; k < 32; k++)
        acc = fmaf(__shfl_sync(0xFFFFFFFFu, xv, k), W2[k * 16 + t], acc);
    if (lane < 16) g_feat2[n * 16 + t] = acc;
    float pl = (lane < 16) ? acc * al2[t] : 0.0f;
    float pr = (lane < 16) ? acc * ar2[t] : 0.0f;
#pragma unroll
    for (int o = 16; o; o >>= 1) {
        pl += __shfl_xor_sync(0xFFFFFFFFu, pl, o);
        pr += __shfl_xor_sync(0xFFFFFFFFu, pr, o);
    }
    if (lane == 0) { g_el2[n] = pl; g_er2[n] = pr; }
}

// ---------------- layer 2: fused softmax + aggregate + log_softmax ----------
__global__ void k_agg2(const float* __restrict__ b2, float* __restrict__ out, int N) {
    __shared__ float s_ex[8][32];
    __shared__ int s_s[8][32];
    int wi = threadIdx.x >> 5;
    int lane = threadIdx.x & 31;
    int n = blockIdx.x * 8 + wi;
    if (n >= N) return;
    int beg = g_off[n], end = g_off[n + 1];
    float ern = g_er2[n];

    float m = -CUDART_INF_F;
    for (int j = beg + lane; j < end; j += 32)
        m = fmaxf(m, leaky(g_el2[g_csr[j]] + ern));
#pragma unroll
    for (int o = 16; o; o >>= 1)
        m = fmaxf(m, __shfl_xor_sync(0xFFFFFFFFu, m, o));

    int eg = lane >> 2;
    int dg = lane & 3;
    float4 acc = make_float4(0.f, 0.f, 0.f, 0.f);
    float psum = 0.f;
    for (int base = beg; base < end; base += 32) {
        int valid = min(32, end - base);
        if (lane < valid) {
            int s = g_csr[base + lane];
            float e = __expf(leaky(g_el2[s] + ern) - m);
            psum += e;
            s_s[wi][lane] = s;
            s_ex[wi][lane] = e;
        }
        __syncwarp();
        for (int j0 = 0; j0 < valid; j0 += 8) {
            int j = j0 + eg;
            if (j < valid) {
                float ex = s_ex[wi][j];
                float4 f = *(const float4*)&g_feat2[s_s[wi][j] * 16 + dg * 4];
                acc.x = fmaf(ex, f.x, acc.x);
                acc.y = fmaf(ex, f.y, acc.y);
                acc.z = fmaf(ex, f.z, acc.z);
                acc.w = fmaf(ex, f.w, acc.w);
            }
        }
        __syncwarp();
    }
#pragma unroll
    for (int o = 4; o <= 16; o <<= 1) {
        acc.x += __shfl_xor_sync(0xFFFFFFFFu, acc.x, o);
        acc.y += __shfl_xor_sync(0xFFFFFFFFu, acc.y, o);
        acc.z += __shfl_xor_sync(0xFFFFFFFFu, acc.z, o);
        acc.w += __shfl_xor_sync(0xFFFFFFFFu, acc.w, o);
    }
#pragma unroll
    for (int o = 16; o; o >>= 1)
        psum += __shfl_xor_sync(0xFFFFFFFFu, psum, o);
    float inv = (psum > 0.f) ? __frcp_rn(psum) : 0.f;
    float4 bb = *(const float4*)&b2[dg * 4];
    float4 val = make_float4(acc.x * inv + bb.x, acc.y * inv + bb.y,
                             acc.z * inv + bb.z, acc.w * inv + bb.w);

    float mm = fmaxf(fmaxf(val.x, val.y), fmaxf(val.z, val.w));
#pragma unroll
    for (int o = 1; o <= 2; o <<= 1)
        mm = fmaxf(mm, __shfl_xor_sync(0xFFFFFFFFu, mm, o));
    float es = __expf(val.x - mm) + __expf(val.y - mm) +
               __expf(val.z - mm) + __expf(val.w - mm);
#pragma unroll
    for (int o = 1; o <= 2; o <<= 1)
        es += __shfl_xor_sync(0xFFFFFFFFu, es, o);
    float lse = mm + logf(es);
    if (lane < 4) {
        *(float4*)&out[n * 16 + dg * 4] =
            make_float4(val.x - lse, val.y - lse, val.z - lse, val.w - lse);
    }
}

// ---------------- launcher ---------------------------------------------------
extern "C" void kernel_launch(void* const* d_in, const int* in_sizes, int n_in,
                              void* d_out, int out_size) {
    const float* features = (const float*)d_in[0];
    const int*   src      = (const int*)  d_in[1];
    const int*   dst      = (const int*)  d_in[2];
    const float* W1       = (const float*)d_in[3];
    const float* al1      = (const float*)d_in[4];
    const float* ar1      = (const float*)d_in[5];
    const float* b1       = (const float*)d_in[6];
    const float* W2       = (const float*)d_in[7];
    const float* al2      = (const float*)d_in[8];
    const float* ar2      = (const float*)d_in[9];
    const float* b2       = (const float*)d_in[10];
    float* out = (float*)d_out;

    int N = in_sizes[0] / 128;
    int E = in_sizes[1];
    int NB = (N + 1023) / 1024;
    int gemm_smem = 2 * 128 * AS_STRIDE * (int)sizeof(__half);

    static int configured = 0;
    if (!configured) {
        cudaFuncSetAttribute(k_gemm1, cudaFuncAttributeMaxDynamicSharedMemorySize, gemm_smem);
        configured = 1;
    }

    k_zero<<<(N + 255) / 256, 256>>>(N);
    k_hist<<<(E + 255) / 256, 256>>>(dst, E);
    k_scanA<<<NB, 1024>>>(N);
    k_scanB<<<1, 64>>>(NB, N);
    k_scanC<<<NB, 1024>>>(N);
    k_scatter<<<(E + 255) / 256, 256>>>(src, dst, E);
    k_cvtW<<<128, 128>>>(W1);
    k_gemm1<<<(N + 127) / 128, 256, gemm_smem>>>(features, N);
    k_elr1<<<(N * 32 + 255) / 256, 256>>>(al1, ar1, N);
    k_agg1<<<(N + 7) / 8, 256>>>(b1, N);
    k_gemm2<<<(N * 32 + 255) / 256, 256>>>(W2, al2, ar2, N);
    k_agg2<<<(N + 7) / 8, 256>>>(b2, out, N);
}

// round 7
// speedup vs baseline: 3.2893x; 1.0332x over previous
#include <cuda_runtime.h>
#include <cuda_fp16.h>
#include <math_constants.h>

#define NN 50000
#define EE 1600000

// ---------------- scratch (device globals) ----------------------------------
__device__ __align__(16) __half g_feat1h[NN * 128];
__device__ __align__(16) __half g_W1t[128 * 128];   // W1 transposed [n][k], fp16
__device__ __align__(16) float g_el1  [NN * 4];
__device__ __align__(16) float g_er1  [NN * 4];
__device__ __align__(16) float g_feat2[NN * 16];
__device__ float g_el2[NN];
__device__ float g_er2[NN];
__device__ int   g_deg[NN];
__device__ int   g_off[NN + 1];
__device__ int   g_csr[EE];
__device__ int   g_rank[EE];
__device__ int   g_bsum[64];
__device__ int   g_ready;

__device__ __forceinline__ float leaky(float v) { return v > 0.0f ? v : 0.2f * v; }

// ---------------- prep: zero deg, reset scan state, convert W1 ---------------
__global__ void k_prep(const float* __restrict__ W1, int N) {
    int i = blockIdx.x * blockDim.x + threadIdx.x;
    if (i < N) g_deg[i] = 0;
    if (i < 128 * 128) {
        int n = i >> 7, k = i & 127;
        g_W1t[n * 128 + k] = __float2half_rn(W1[k * 128 + n]);
    }
    if (i == 0) g_ready = 0;
}

// ---------------- histogram (rank = atomic return) ---------------------------
__global__ void k_hist(const int* __restrict__ dst, int E) {
    int e = blockIdx.x * blockDim.x + threadIdx.x;
    if (e < E) g_rank[e] = atomicAdd(&g_deg[dst[e]], 1);
}

// ---------------- single-launch scan (all blocks resident) -------------------
__global__ void k_scan(int N, int NB) {
    __shared__ int sm[1024];
    __shared__ int s_carry;
    int t = threadIdx.x, b = blockIdx.x;
    int i = b * 1024 + t;
    int v = (i < N) ? g_deg[i] : 0;
    sm[t] = v;
    __syncthreads();
#pragma unroll
    for (int o = 1; o < 1024; o <<= 1) {
        int a = (t >= o) ? sm[t - o] : 0;
        __syncthreads();
        sm[t] += a;
        __syncthreads();
    }
    int incl = sm[t];
    // publish block aggregate, then warp 0 waits for all and computes carry
    if (t == 0) {
        g_bsum[b] = sm[1023];
        __threadfence();
        atomicAdd(&g_ready, 1);
    }
    if (t < 32) {
        while (*(volatile int*)&g_ready < NB) {}
        __threadfence();
        int a = (t < b) ? g_bsum[t] : 0;
        if (t + 32 < b) a += g_bsum[t + 32];
#pragma unroll
        for (int o = 16; o; o >>= 1) a += __shfl_xor_sync(0xFFFFFFFFu, a, o);
        if (t == 0) s_carry = a;
    }
    __syncthreads();
    if (i < N) g_off[i] = s_carry + incl - v;
    if (b == NB - 1 && t == 0) g_off[N] = s_carry + sm[1023];
}

// ---------------- scatter (no atomics) ---------------------------------------
__global__ void k_scatter(const int* __restrict__ src, const int* __restrict__ dst, int E) {
    int e = blockIdx.x * blockDim.x + threadIdx.x;
    if (e >= E) return;
    g_csr[g_off[dst[e]] + g_rank[e]] = src[e];
}

// ---------------- layer 1 GEMM (tensor cores) + fused el/er ------------------
#define AS_STRIDE 136
__global__ void k_gemm1(const float* __restrict__ x,
                        const float* __restrict__ al1, const float* __restrict__ ar1, int N) {
    extern __shared__ __align__(16) __half smem[];
    __half* As = smem;                     // [128][136]
    __half* Ws = smem + 128 * AS_STRIDE;   // [128][136]  (W1t: [n][k])
    int t = threadIdx.x;
    int m0 = blockIdx.x * 128;

    {
        int r = t >> 1;
        int c0 = (t & 1) * 64;
        const uint4* srcp = (const uint4*)&g_W1t[r * 128 + c0];
        uint4* dstp = (uint4*)&Ws[r * AS_STRIDE + c0];
#pragma unroll
        for (int i = 0; i < 8; i++) dstp[i] = srcp[i];
    }
    {
        int r = t >> 1;
        int c0 = (t & 1) * 64;
        int m = m0 + r;
#pragma unroll
        for (int i = 0; i < 64; i += 4) {
            float4 v = (m < N) ? *(const float4*)&x[m * 128 + c0 + i]
                               : make_float4(0.f, 0.f, 0.f, 0.f);
            __half2 h01 = __floats2half2_rn(v.x, v.y);
            __half2 h23 = __floats2half2_rn(v.z, v.w);
            uint2 pk;
            pk.x = *(unsigned*)&h01;
            pk.y = *(unsigned*)&h23;
            *(uint2*)&As[r * AS_STRIDE + c0 + i] = pk;
        }
    }
    __syncthreads();

    int w = t >> 5, lane = t & 31;
    int g = lane >> 2, tg = lane & 3;
    int mrow = w * 16;

    float acc[16][4];
#pragma unroll
    for (int nt = 0; nt < 16; nt++)
#pragma unroll
        for (int i = 0; i < 4; i++) acc[nt][i] = 0.f;

#pragma unroll
    for (int k0 = 0; k0 < 128; k0 += 16) {
        unsigned ra0 = *(const unsigned*)&As[(mrow + g)     * AS_STRIDE + k0 + tg * 2];
        unsigned ra1 = *(const unsigned*)&As[(mrow + g + 8) * AS_STRIDE + k0 + tg * 2];
        unsigned ra2 = *(const unsigned*)&As[(mrow + g)     * AS_STRIDE + k0 + tg * 2 + 8];
        unsigned ra3 = *(const unsigned*)&As[(mrow + g + 8) * AS_STRIDE + k0 + tg * 2 + 8];
#pragma unroll
        for (int nt = 0; nt < 16; nt++) {
            unsigned rb0 = *(const unsigned*)&Ws[(nt * 8 + g) * AS_STRIDE + k0 + tg * 2];
            unsigned rb1 = *(const unsigned*)&Ws[(nt * 8 + g) * AS_STRIDE + k0 + tg * 2 + 8];
            asm volatile(
                "mma.sync.aligned.m16n8k16.row.col.f32.f16.f16.f32 "
                "{%0,%1,%2,%3}, {%4,%5,%6,%7}, {%8,%9}, {%0,%1,%2,%3};"
                : "+f"(acc[nt][0]), "+f"(acc[nt][1]), "+f"(acc[nt][2]), "+f"(acc[nt][3])
                : "r"(ra0), "r"(ra1), "r"(ra2), "r"(ra3), "r"(rb0), "r"(rb1));
        }
    }

    int m_g = m0 + mrow + g;
    int m_g8 = m_g + 8;
    if (m_g < N) {
#pragma unroll
        for (int nt = 0; nt < 16; nt++) {
            __half2 h = __floats2half2_rn(acc[nt][0], acc[nt][1]);
            *(__half2*)&g_feat1h[m_g * 128 + nt * 8 + tg * 2] = h;
        }
    }
    if (m_g8 < N) {
#pragma unroll
        for (int nt = 0; nt < 16; nt++) {
            __half2 h = __floats2half2_rn(acc[nt][2], acc[nt][3]);
            *(__half2*)&g_feat1h[m_g8 * 128 + nt * 8 + tg * 2] = h;
        }
    }

    // fused el/er from fp32 accumulators (head h = nt>>2)
    float pl0[4] = {0, 0, 0, 0}, pr0[4] = {0, 0, 0, 0};
    float pl1[4] = {0, 0, 0, 0}, pr1[4] = {0, 0, 0, 0};
#pragma unroll
    for (int nt = 0; nt < 16; nt++) {
        float2 a = *(const float2*)&al1[nt * 8 + tg * 2];
        float2 r = *(const float2*)&ar1[nt * 8 + tg * 2];
        int h = nt >> 2;
        pl0[h] += acc[nt][0] * a.x + acc[nt][1] * a.y;
        pr0[h] += acc[nt][0] * r.x + acc[nt][1] * r.y;
        pl1[h] += acc[nt][2] * a.x + acc[nt][3] * a.y;
        pr1[h] += acc[nt][2] * r.x + acc[nt][3] * r.y;
    }
#pragma unroll
    for (int h = 0; h < 4; h++) {
#pragma unroll
        for (int o = 1; o <= 2; o <<= 1) {
            pl0[h] += __shfl_xor_sync(0xFFFFFFFFu, pl0[h], o);
            pr0[h] += __shfl_xor_sync(0xFFFFFFFFu, pr0[h], o);
            pl1[h] += __shfl_xor_sync(0xFFFFFFFFu, pl1[h], o);
            pr1[h] += __shfl_xor_sync(0xFFFFFFFFu, pr1[h], o);
        }
    }
    // lane tg stores head tg
    float el0 = (tg == 0) ? pl0[0] : (tg == 1) ? pl0[1] : (tg == 2) ? pl0[2] : pl0[3];
    float er0 = (tg == 0) ? pr0[0] : (tg == 1) ? pr0[1] : (tg == 2) ? pr0[2] : pr0[3];
    float el1v = (tg == 0) ? pl1[0] : (tg == 1) ? pl1[1] : (tg == 2) ? pl1[2] : pl1[3];
    float er1v = (tg == 0) ? pr1[0] : (tg == 1) ? pr1[1] : (tg == 2) ? pr1[2] : pr1[3];
    if (m_g < N)  { g_el1[m_g * 4 + tg] = el0;  g_er1[m_g * 4 + tg] = er0; }
    if (m_g8 < N) { g_el1[m_g8 * 4 + tg] = el1v; g_er1[m_g8 * 4 + tg] = er1v; }
}

// ---------------- layer 1 agg + finalize + fused layer-2 GEMM ----------------
__global__ void k_agg1(const float* __restrict__ b1, const float* __restrict__ W2,
                       const float* __restrict__ al2, const float* __restrict__ ar2, int N) {
    __shared__ __align__(16) float s_ex[8][128];
    __shared__ int s_s[8][32];
    int wi = threadIdx.x >> 5;
    int lane = threadIdx.x & 31;
    int n = blockIdx.x * 8 + wi;
    if (n >= N) return;
    int beg = g_off[n], end = g_off[n + 1];
    float4 er = *(const float4*)&g_er1[n * 4];

    // pass 1: per-head max
    float m0 = -CUDART_INF_F, m1 = -CUDART_INF_F, m2 = -CUDART_INF_F, m3 = -CUDART_INF_F;
    for (int j = beg + lane; j < end; j += 32) {
        int s = g_csr[j];
        float4 el = *(const float4*)&g_el1[s * 4];
        m0 = fmaxf(m0, leaky(el.x + er.x));
        m1 = fmaxf(m1, leaky(el.y + er.y));
        m2 = fmaxf(m2, leaky(el.z + er.z));
        m3 = fmaxf(m3, leaky(el.w + er.w));
    }
#pragma unroll
    for (int o = 16; o; o >>= 1) {
        m0 = fmaxf(m0, __shfl_xor_sync(0xFFFFFFFFu, m0, o));
        m1 = fmaxf(m1, __shfl_xor_sync(0xFFFFFFFFu, m1, o));
        m2 = fmaxf(m2, __shfl_xor_sync(0xFFFFFFFFu, m2, o));
        m3 = fmaxf(m3, __shfl_xor_sync(0xFFFFFFFFu, m3, o));
    }

    // pass 2: exp + sum + weighted aggregate
    int e2 = lane >> 4;
    int lh = lane & 15;
    int h  = lh >> 2;
    float acc[8];
#pragma unroll
    for (int i = 0; i < 8; i++) acc[i] = 0.f;
    float sm0 = 0.f, sm1 = 0.f, sm2 = 0.f, sm3 = 0.f;

    for (int base = beg; base < end; base += 32) {
        int valid = min(32, end - base);
        if (lane < valid) {
            int s = g_csr[base + lane];
            float4 el = *(const float4*)&g_el1[s * 4];
            float e0 = __expf(leaky(el.x + er.x) - m0);
            float e1 = __expf(leaky(el.y + er.y) - m1);
            float e2f = __expf(leaky(el.z + er.z) - m2);
            float e3 = __expf(leaky(el.w + er.w) - m3);
            sm0 += e0; sm1 += e1; sm2 += e2f; sm3 += e3;
            s_s[wi][lane] = s;
            *(float4*)&s_ex[wi][lane * 4] = make_float4(e0, e1, e2f, e3);
        }
        __syncwarp();
#pragma unroll 2
        for (int j0 = 0; j0 < valid; j0 += 2) {
            int j = j0 + e2;
            if (j < valid) {
                float ex = s_ex[wi][j * 4 + h];
                int sj = s_s[wi][j];
                uint4 u = *(const uint4*)&g_feat1h[sj * 128 + lh * 8];
                float2 f0 = __half22float2(*(const __half2*)&u.x);
                float2 f1 = __half22float2(*(const __half2*)&u.y);
                float2 f2 = __half22float2(*(const __half2*)&u.z);
                float2 f3 = __half22float2(*(const __half2*)&u.w);
                acc[0] = fmaf(ex, f0.x, acc[0]);
                acc[1] = fmaf(ex, f0.y, acc[1]);
                acc[2] = fmaf(ex, f1.x, acc[2]);
                acc[3] = fmaf(ex, f1.y, acc[3]);
                acc[4] = fmaf(ex, f2.x, acc[4]);
                acc[5] = fmaf(ex, f2.y, acc[5]);
                acc[6] = fmaf(ex, f3.x, acc[6]);
                acc[7] = fmaf(ex, f3.y, acc[7]);
            }
        }
        __syncwarp();
    }
#pragma unroll
    for (int i = 0; i < 8; i++) acc[i] += __shfl_xor_sync(0xFFFFFFFFu, acc[i], 16);
#pragma unroll
    for (int o = 16; o; o >>= 1) {
        sm0 += __shfl_xor_sync(0xFFFFFFFFu, sm0, o);
        sm1 += __shfl_xor_sync(0xFFFFFFFFu, sm1, o);
        sm2 += __shfl_xor_sync(0xFFFFFFFFu, sm2, o);
        sm3 += __shfl_xor_sync(0xFFFFFFFFu, sm3, o);
    }
    float ssum = (h == 0) ? sm0 : (h == 1) ? sm1 : (h == 2) ? sm2 : sm3;
    float inv = (ssum > 0.f) ? __frcp_rn(ssum) : 0.f;
    float4 ba = *(const float4*)&b1[lh * 8];
    float4 bb = *(const float4*)&b1[lh * 8 + 4];
    float v[8];
    v[0] = fmaxf(acc[0] * inv + ba.x, 0.f);
    v[1] = fmaxf(acc[1] * inv + ba.y, 0.f);
    v[2] = fmaxf(acc[2] * inv + ba.z, 0.f);
    v[3] = fmaxf(acc[3] * inv + ba.w, 0.f);
    v[4] = fmaxf(acc[4] * inv + bb.x, 0.f);
    v[5] = fmaxf(acc[5] * inv + bb.y, 0.f);
    v[6] = fmaxf(acc[6] * inv + bb.z, 0.f);
    v[7] = fmaxf(acc[7] * inv + bb.w, 0.f);
#pragma unroll
    for (int o = 4; o <= 8; o <<= 1)
#pragma unroll
        for (int i = 0; i < 8; i++) v[i] += __shfl_xor_sync(0xFFFFFFFFu, v[i], o);

    // ---- fused layer-2 GEMM + el2/er2 (x1 staged through this warp's smem) --
    float* s_x1 = &s_ex[wi][0];
    if (lane < 4) {
#pragma unroll
        for (int i = 0; i < 8; i++) s_x1[lane * 8 + i] = v[i] * 0.25f;
    }
    __syncwarp();
    int t16 = lane & 15;
    float f2 = 0.f;
#pragma unroll
    for (int k = 0; k < 32; k++)
        f2 = fmaf(s_x1[k], W2[k * 16 + t16], f2);
    if (lane < 16) g_feat2[n * 16 + t16] = f2;
    float pl = f2 * al2[t16];
    float pr = f2 * ar2[t16];
#pragma unroll
    for (int o = 1; o <= 8; o <<= 1) {
        pl += __shfl_xor_sync(0xFFFFFFFFu, pl, o);
        pr += __shfl_xor_sync(0xFFFFFFFFu, pr, o);
    }
    if (lane == 0) { g_el2[n] = pl; g_er2[n] = pr; }
}

// ---------------- layer 2: fused softmax + aggregate + log_softmax ----------
__global__ void k_agg2(const float* __restrict__ b2, float* __restrict__ out, int N) {
    __shared__ float s_ex[8][32];
    __shared__ int s_s[8][32];
    int wi = threadIdx.x >> 5;
    int lane = threadIdx.x & 31;
    int n = blockIdx.x * 8 + wi;
    if (n >= N) return;
    int beg = g_off[n], end = g_off[n + 1];
    float ern = g_er2[n];

    float m = -CUDART_INF_F;
    for (int j = beg + lane; j < end; j += 32)
        m = fmaxf(m, leaky(g_el2[g_csr[j]] + ern));
#pragma unroll
    for (int o = 16; o; o >>= 1)
        m = fmaxf(m, __shfl_xor_sync(0xFFFFFFFFu, m, o));

    int eg = lane >> 2;
    int dg = lane & 3;
    float4 acc = make_float4(0.f, 0.f, 0.f, 0.f);
    float psum = 0.f;
    for (int base = beg; base < end; base += 32) {
        int valid = min(32, end - base);
        if (lane < valid) {
            int s = g_csr[base + lane];
            float e = __expf(leaky(g_el2[s] + ern) - m);
            psum += e;
            s_s[wi][lane] = s;
            s_ex[wi][lane] = e;
        }
        __syncwarp();
        for (int j0 = 0; j0 < valid; j0 += 8) {
            int j = j0 + eg;
            if (j < valid) {
                float ex = s_ex[wi][j];
                float4 f = *(const float4*)&g_feat2[s_s[wi][j] * 16 + dg * 4];
                acc.x = fmaf(ex, f.x, acc.x);
                acc.y = fmaf(ex, f.y, acc.y);
                acc.z = fmaf(ex, f.z, acc.z);
                acc.w = fmaf(ex, f.w, acc.w);
            }
        }
        __syncwarp();
    }
#pragma unroll
    for (int o = 4; o <= 16; o <<= 1) {
        acc.x += __shfl_xor_sync(0xFFFFFFFFu, acc.x, o);
        acc.y += __shfl_xor_sync(0xFFFFFFFFu, acc.y, o);
        acc.z += __shfl_xor_sync(0xFFFFFFFFu, acc.z, o);
        acc.w += __shfl_xor_sync(0xFFFFFFFFu, acc.w, o);
    }
#pragma unroll
    for (int o = 16; o; o >>= 1)
        psum += __shfl_xor_sync(0xFFFFFFFFu, psum, o);
    float inv = (psum > 0.f) ? __frcp_rn(psum) : 0.f;
    float4 bb = *(const float4*)&b2[dg * 4];
    float4 val = make_float4(acc.x * inv + bb.x, acc.y * inv + bb.y,
                             acc.z * inv + bb.z, acc.w * inv + bb.w);

    float mm = fmaxf(fmaxf(val.x, val.y), fmaxf(val.z, val.w));
#pragma unroll
    for (int o = 1; o <= 2; o <<= 1)
        mm = fmaxf(mm, __shfl_xor_sync(0xFFFFFFFFu, mm, o));
    float es = __expf(val.x - mm) + __expf(val.y - mm) +
               __expf(val.z - mm) + __expf(val.w - mm);
#pragma unroll
    for (int o = 1; o <= 2; o <<= 1)
        es += __shfl_xor_sync(0xFFFFFFFFu, es, o);
    float lse = mm + logf(es);
    if (lane < 4) {
        *(float4*)&out[n * 16 + dg * 4] =
            make_float4(val.x - lse, val.y - lse, val.z - lse, val.w - lse);
    }
}

// ---------------- launcher ---------------------------------------------------
extern "C" void kernel_launch(void* const* d_in, const int* in_sizes, int n_in,
                              void* d_out, int out_size) {
    const float* features = (const float*)d_in[0];
    const int*   src      = (const int*)  d_in[1];
    const int*   dst      = (const int*)  d_in[2];
    const float* W1       = (const float*)d_in[3];
    const float* al1      = (const float*)d_in[4];
    const float* ar1      = (const float*)d_in[5];
    const float* b1       = (const float*)d_in[6];
    const float* W2       = (const float*)d_in[7];
    const float* al2      = (const float*)d_in[8];
    const float* ar2      = (const float*)d_in[9];
    const float* b2       = (const float*)d_in[10];
    float* out = (float*)d_out;

    int N = in_sizes[0] / 128;
    int E = in_sizes[1];
    int NB = (N + 1023) / 1024;
    int gemm_smem = 2 * 128 * AS_STRIDE * (int)sizeof(__half);

    static int configured = 0;
    if (!configured) {
        cudaFuncSetAttribute(k_gemm1, cudaFuncAttributeMaxDynamicSharedMemorySize, gemm_smem);
        configured = 1;
    }

    k_prep<<<(N + 255) / 256, 256>>>(W1, N);
    k_hist<<<(E + 255) / 256, 256>>>(dst, E);
    k_scan<<<NB, 1024>>>(N, NB);
    k_scatter<<<(E + 255) / 256, 256>>>(src, dst, E);
    k_gemm1<<<(N + 127) / 128, 256, gemm_smem>>>(features, al1, ar1, N);
    k_agg1<<<(N + 7) / 8, 256>>>(b1, W2, al2, ar2, N);
    k_agg2<<<(N + 7) / 8, 256>>>(b2, out, N);
}

// round 8
// speedup vs baseline: 3.4888x; 1.0607x over previous
#include <cuda_runtime.h>
#include <cuda_fp16.h>
#include <math_constants.h>

#define NN 50000
#define EE 1600000

// ---------------- scratch (device globals) ----------------------------------
__device__ __align__(16) __half g_feat1h[NN * 128];
__device__ __align__(16) __half g_W1t[128 * 128];   // W1 transposed [n][k], fp16
__device__ __align__(16) float g_el1  [NN * 4];
__device__ __align__(16) float g_er1  [NN * 4];
__device__ __align__(16) float g_feat2[NN * 16];
__device__ float g_el2[NN];
__device__ float g_er2[NN];
__device__ int   g_deg[NN];
__device__ int   g_off[NN + 1];
__device__ int   g_csr[EE];
__device__ __align__(16) int g_rank[EE];
__device__ int   g_bsum[64];
__device__ int   g_ready;

__device__ __forceinline__ float leaky(float v) { return v > 0.0f ? v : 0.2f * v; }

// ---------------- prep: zero deg, reset scan state, convert W1 ---------------
__global__ void k_prep(const float* __restrict__ W1, int N) {
    int i = blockIdx.x * blockDim.x + threadIdx.x;
    if (i < N) g_deg[i] = 0;
    if (i < 128 * 128) {
        int n = i >> 7, k = i & 127;
        g_W1t[n * 128 + k] = __float2half_rn(W1[k * 128 + n]);
    }
    if (i == 0) g_ready = 0;
}

// ---------------- histogram: 4 edges/thread, MLP=4 ---------------------------
__global__ void k_hist(const int* __restrict__ dst, int E) {
    int e0 = (blockIdx.x * blockDim.x + threadIdx.x) * 4;
    if (e0 + 3 < E) {
        int4 d = *(const int4*)&dst[e0];
        int4 r;
        r.x = atomicAdd(&g_deg[d.x], 1);
        r.y = atomicAdd(&g_deg[d.y], 1);
        r.z = atomicAdd(&g_deg[d.z], 1);
        r.w = atomicAdd(&g_deg[d.w], 1);
        *(int4*)&g_rank[e0] = r;
    } else {
        for (int e = e0; e < E; e++)
            g_rank[e] = atomicAdd(&g_deg[dst[e]], 1);
    }
}

// ---------------- single-launch scan (all blocks resident) -------------------
__global__ void k_scan(int N, int NB) {
    __shared__ int sm[1024];
    __shared__ int s_carry;
    int t = threadIdx.x, b = blockIdx.x;
    int i = b * 1024 + t;
    int v = (i < N) ? g_deg[i] : 0;
    sm[t] = v;
    __syncthreads();
#pragma unroll
    for (int o = 1; o < 1024; o <<= 1) {
        int a = (t >= o) ? sm[t - o] : 0;
        __syncthreads();
        sm[t] += a;
        __syncthreads();
    }
    int incl = sm[t];
    if (t == 0) {
        g_bsum[b] = sm[1023];
        __threadfence();
        atomicAdd(&g_ready, 1);
    }
    if (t < 32) {
        while (*(volatile int*)&g_ready < NB) {}
        __threadfence();
        int a = (t < b) ? g_bsum[t] : 0;
        if (t + 32 < b) a += g_bsum[t + 32];
#pragma unroll
        for (int o = 16; o; o >>= 1) a += __shfl_xor_sync(0xFFFFFFFFu, a, o);
        if (t == 0) s_carry = a;
    }
    __syncthreads();
    if (i < N) g_off[i] = s_carry + incl - v;
    if (b == NB - 1 && t == 0) g_off[N] = s_carry + sm[1023];
}

// ---------------- scatter: 4 edges/thread, MLP=4, no atomics -----------------
__global__ void k_scatter(const int* __restrict__ src, const int* __restrict__ dst, int E) {
    int e0 = (blockIdx.x * blockDim.x + threadIdx.x) * 4;
    if (e0 + 3 < E) {
        int4 d = *(const int4*)&dst[e0];
        int4 r = *(const int4*)&g_rank[e0];
        int4 s = *(const int4*)&src[e0];
        int o0 = g_off[d.x], o1 = g_off[d.y], o2 = g_off[d.z], o3 = g_off[d.w];
        g_csr[o0 + r.x] = s.x;
        g_csr[o1 + r.y] = s.y;
        g_csr[o2 + r.z] = s.z;
        g_csr[o3 + r.w] = s.w;
    } else {
        for (int e = e0; e < E; e++)
            g_csr[g_off[dst[e]] + g_rank[e]] = src[e];
    }
}

// ---------------- layer 1 GEMM (tensor cores) + fused el/er ------------------
#define AS_STRIDE 136
__global__ void k_gemm1(const float* __restrict__ x,
                        const float* __restrict__ al1, const float* __restrict__ ar1, int N) {
    extern __shared__ __align__(16) __half smem[];
    __half* As = smem;                     // [128][136]
    __half* Ws = smem + 128 * AS_STRIDE;   // [128][136]  (W1t: [n][k])
    int t = threadIdx.x;
    int m0 = blockIdx.x * 128;

    {
        int r = t >> 1;
        int c0 = (t & 1) * 64;
        const uint4* srcp = (const uint4*)&g_W1t[r * 128 + c0];
        uint4* dstp = (uint4*)&Ws[r * AS_STRIDE + c0];
#pragma unroll
        for (int i = 0; i < 8; i++) dstp[i] = srcp[i];
    }
    {
        int r = t >> 1;
        int c0 = (t & 1) * 64;
        int m = m0 + r;
#pragma unroll
        for (int i = 0; i < 64; i += 4) {
            float4 v = (m < N) ? *(const float4*)&x[m * 128 + c0 + i]
                               : make_float4(0.f, 0.f, 0.f, 0.f);
            __half2 h01 = __floats2half2_rn(v.x, v.y);
            __half2 h23 = __floats2half2_rn(v.z, v.w);
            uint2 pk;
            pk.x = *(unsigned*)&h01;
            pk.y = *(unsigned*)&h23;
            *(uint2*)&As[r * AS_STRIDE + c0 + i] = pk;
        }
    }
    __syncthreads();

    int w = t >> 5, lane = t & 31;
    int g = lane >> 2, tg = lane & 3;
    int mrow = w * 16;

    float acc[16][4];
#pragma unroll
    for (int nt = 0; nt < 16; nt++)
#pragma unroll
        for (int i = 0; i < 4; i++) acc[nt][i] = 0.f;

#pragma unroll
    for (int k0 = 0; k0 < 128; k0 += 16) {
        unsigned ra0 = *(const unsigned*)&As[(mrow + g)     * AS_STRIDE + k0 + tg * 2];
        unsigned ra1 = *(const unsigned*)&As[(mrow + g + 8) * AS_STRIDE + k0 + tg * 2];
        unsigned ra2 = *(const unsigned*)&As[(mrow + g)     * AS_STRIDE + k0 + tg * 2 + 8];
        unsigned ra3 = *(const unsigned*)&As[(mrow + g + 8) * AS_STRIDE + k0 + tg * 2 + 8];
#pragma unroll
        for (int nt = 0; nt < 16; nt++) {
            unsigned rb0 = *(const unsigned*)&Ws[(nt * 8 + g) * AS_STRIDE + k0 + tg * 2];
            unsigned rb1 = *(const unsigned*)&Ws[(nt * 8 + g) * AS_STRIDE + k0 + tg * 2 + 8];
            asm volatile(
                "mma.sync.aligned.m16n8k16.row.col.f32.f16.f16.f32 "
                "{%0,%1,%2,%3}, {%4,%5,%6,%7}, {%8,%9}, {%0,%1,%2,%3};"
                : "+f"(acc[nt][0]), "+f"(acc[nt][1]), "+f"(acc[nt][2]), "+f"(acc[nt][3])
                : "r"(ra0), "r"(ra1), "r"(ra2), "r"(ra3), "r"(rb0), "r"(rb1));
        }
    }

    int m_g = m0 + mrow + g;
    int m_g8 = m_g + 8;
    if (m_g < N) {
#pragma unroll
        for (int nt = 0; nt < 16; nt++) {
            __half2 h = __floats2half2_rn(acc[nt][0], acc[nt][1]);
            *(__half2*)&g_feat1h[m_g * 128 + nt * 8 + tg * 2] = h;
        }
    }
    if (m_g8 < N) {
#pragma unroll
        for (int nt = 0; nt < 16; nt++) {
            __half2 h = __floats2half2_rn(acc[nt][2], acc[nt][3]);
            *(__half2*)&g_feat1h[m_g8 * 128 + nt * 8 + tg * 2] = h;
        }
    }

    // fused el/er from fp32 accumulators (head h = nt>>2)
    float pl0[4] = {0, 0, 0, 0}, pr0[4] = {0, 0, 0, 0};
    float pl1[4] = {0, 0, 0, 0}, pr1[4] = {0, 0, 0, 0};
#pragma unroll
    for (int nt = 0; nt < 16; nt++) {
        float2 a = *(const float2*)&al1[nt * 8 + tg * 2];
        float2 r = *(const float2*)&ar1[nt * 8 + tg * 2];
        int h = nt >> 2;
        pl0[h] += acc[nt][0] * a.x + acc[nt][1] * a.y;
        pr0[h] += acc[nt][0] * r.x + acc[nt][1] * r.y;
        pl1[h] += acc[nt][2] * a.x + acc[nt][3] * a.y;
        pr1[h] += acc[nt][2] * r.x + acc[nt][3] * r.y;
    }
#pragma unroll
    for (int h = 0; h < 4; h++) {
#pragma unroll
        for (int o = 1; o <= 2; o <<= 1) {
            pl0[h] += __shfl_xor_sync(0xFFFFFFFFu, pl0[h], o);
            pr0[h] += __shfl_xor_sync(0xFFFFFFFFu, pr0[h], o);
            pl1[h] += __shfl_xor_sync(0xFFFFFFFFu, pl1[h], o);
            pr1[h] += __shfl_xor_sync(0xFFFFFFFFu, pr1[h], o);
        }
    }
    float el0 = (tg == 0) ? pl0[0] : (tg == 1) ? pl0[1] : (tg == 2) ? pl0[2] : pl0[3];
    float er0 = (tg == 0) ? pr0[0] : (tg == 1) ? pr0[1] : (tg == 2) ? pr0[2] : pr0[3];
    float el1v = (tg == 0) ? pl1[0] : (tg == 1) ? pl1[1] : (tg == 2) ? pl1[2] : pl1[3];
    float er1v = (tg == 0) ? pr1[0] : (tg == 1) ? pr1[1] : (tg == 2) ? pr1[2] : pr1[3];
    if (m_g < N)  { g_el1[m_g * 4 + tg] = el0;  g_er1[m_g * 4 + tg] = er0; }
    if (m_g8 < N) { g_el1[m_g8 * 4 + tg] = el1v; g_er1[m_g8 * 4 + tg] = er1v; }
}

// ---------------- layer 1 agg (no max pass) + finalize + fused layer-2 GEMM --
__global__ void k_agg1(const float* __restrict__ b1, const float* __restrict__ W2,
                       const float* __restrict__ al2, const float* __restrict__ ar2, int N) {
    __shared__ __align__(16) float s_ex[8][128];
    __shared__ int s_s[8][32];
    int wi = threadIdx.x >> 5;
    int lane = threadIdx.x & 31;
    int n = blockIdx.x * 8 + wi;
    if (n >= N) return;
    int beg = g_off[n], end = g_off[n + 1];
    float4 er = *(const float4*)&g_er1[n * 4];

    // exp + sum + weighted aggregate (softmax is shift-invariant; args are O(1))
    int e2 = lane >> 4;
    int lh = lane & 15;
    int h  = lh >> 2;
    float acc[8];
#pragma unroll
    for (int i = 0; i < 8; i++) acc[i] = 0.f;
    float sm0 = 0.f, sm1 = 0.f, sm2 = 0.f, sm3 = 0.f;

    for (int base = beg; base < end; base += 32) {
        int valid = min(32, end - base);
        if (lane < valid) {
            int s = g_csr[base + lane];
            float4 el = *(const float4*)&g_el1[s * 4];
            float e0 = __expf(leaky(el.x + er.x));
            float e1 = __expf(leaky(el.y + er.y));
            float e2f = __expf(leaky(el.z + er.z));
            float e3 = __expf(leaky(el.w + er.w));
            sm0 += e0; sm1 += e1; sm2 += e2f; sm3 += e3;
            s_s[wi][lane] = s;
            *(float4*)&s_ex[wi][lane * 4] = make_float4(e0, e1, e2f, e3);
        }
        __syncwarp();
#pragma unroll 2
        for (int j0 = 0; j0 < valid; j0 += 2) {
            int j = j0 + e2;
            if (j < valid) {
                float ex = s_ex[wi][j * 4 + h];
                int sj = s_s[wi][j];
                uint4 u = *(const uint4*)&g_feat1h[sj * 128 + lh * 8];
                float2 f0 = __half22float2(*(const __half2*)&u.x);
                float2 f1 = __half22float2(*(const __half2*)&u.y);
                float2 f2 = __half22float2(*(const __half2*)&u.z);
                float2 f3 = __half22float2(*(const __half2*)&u.w);
                acc[0] = fmaf(ex, f0.x, acc[0]);
                acc[1] = fmaf(ex, f0.y, acc[1]);
                acc[2] = fmaf(ex, f1.x, acc[2]);
                acc[3] = fmaf(ex, f1.y, acc[3]);
                acc[4] = fmaf(ex, f2.x, acc[4]);
                acc[5] = fmaf(ex, f2.y, acc[5]);
                acc[6] = fmaf(ex, f3.x, acc[6]);
                acc[7] = fmaf(ex, f3.y, acc[7]);
            }
        }
        __syncwarp();
    }
#pragma unroll
    for (int i = 0; i < 8; i++) acc[i] += __shfl_xor_sync(0xFFFFFFFFu, acc[i], 16);
#pragma unroll
    for (int o = 16; o; o >>= 1) {
        sm0 += __shfl_xor_sync(0xFFFFFFFFu, sm0, o);
        sm1 += __shfl_xor_sync(0xFFFFFFFFu, sm1, o);
        sm2 += __shfl_xor_sync(0xFFFFFFFFu, sm2, o);
        sm3 += __shfl_xor_sync(0xFFFFFFFFu, sm3, o);
    }
    float ssum = (h == 0) ? sm0 : (h == 1) ? sm1 : (h == 2) ? sm2 : sm3;
    float inv = (ssum > 0.f) ? __frcp_rn(ssum) : 0.f;
    float4 ba = *(const float4*)&b1[lh * 8];
    float4 bb = *(const float4*)&b1[lh * 8 + 4];
    float v[8];
    v[0] = fmaxf(acc[0] * inv + ba.x, 0.f);
    v[1] = fmaxf(acc[1] * inv + ba.y, 0.f);
    v[2] = fmaxf(acc[2] * inv + ba.z, 0.f);
    v[3] = fmaxf(acc[3] * inv + ba.w, 0.f);
    v[4] = fmaxf(acc[4] * inv + bb.x, 0.f);
    v[5] = fmaxf(acc[5] * inv + bb.y, 0.f);
    v[6] = fmaxf(acc[6] * inv + bb.z, 0.f);
    v[7] = fmaxf(acc[7] * inv + bb.w, 0.f);
#pragma unroll
    for (int o = 4; o <= 8; o <<= 1)
#pragma unroll
        for (int i = 0; i < 8; i++) v[i] += __shfl_xor_sync(0xFFFFFFFFu, v[i], o);

    // ---- fused layer-2 GEMM + el2/er2 (x1 staged through this warp's smem) --
    float* s_x1 = &s_ex[wi][0];
    if (lane < 4) {
#pragma unroll
        for (int i = 0; i < 8; i++) s_x1[lane * 8 + i] = v[i] * 0.25f;
    }
    __syncwarp();
    int t16 = lane & 15;
    float f2 = 0.f;
#pragma unroll
    for (int k = 0; k < 32; k++)
        f2 = fmaf(s_x1[k], W2[k * 16 + t16], f2);
    if (lane < 16) g_feat2[n * 16 + t16] = f2;
    float pl = f2 * al2[t16];
    float pr = f2 * ar2[t16];
#pragma unroll
    for (int o = 1; o <= 8; o <<= 1) {
        pl += __shfl_xor_sync(0xFFFFFFFFu, pl, o);
        pr += __shfl_xor_sync(0xFFFFFFFFu, pr, o);
    }
    if (lane == 0) { g_el2[n] = pl; g_er2[n] = pr; }
}

// ---------------- layer 2 agg (no max pass) + log_softmax --------------------
__global__ void k_agg2(const float* __restrict__ b2, float* __restrict__ out, int N) {
    __shared__ float s_ex[8][32];
    __shared__ int s_s[8][32];
    int wi = threadIdx.x >> 5;
    int lane = threadIdx.x & 31;
    int n = blockIdx.x * 8 + wi;
    if (n >= N) return;
    int beg = g_off[n], end = g_off[n + 1];
    float ern = g_er2[n];

    int eg = lane >> 2;
    int dg = lane & 3;
    float4 acc = make_float4(0.f, 0.f, 0.f, 0.f);
    float psum = 0.f;
    for (int base = beg; base < end; base += 32) {
        int valid = min(32, end - base);
        if (lane < valid) {
            int s = g_csr[base + lane];
            float e = __expf(leaky(g_el2[s] + ern));
            psum += e;
            s_s[wi][lane] = s;
            s_ex[wi][lane] = e;
        }
        __syncwarp();
        for (int j0 = 0; j0 < valid; j0 += 8) {
            int j = j0 + eg;
            if (j < valid) {
                float ex = s_ex[wi][j];
                float4 f = *(const float4*)&g_feat2[s_s[wi][j] * 16 + dg * 4];
                acc.x = fmaf(ex, f.x, acc.x);
                acc.y = fmaf(ex, f.y, acc.y);
                acc.z = fmaf(ex, f.z, acc.z);
                acc.w = fmaf(ex, f.w, acc.w);
            }
        }
        __syncwarp();
    }
#pragma unroll
    for (int o = 4; o <= 16; o <<= 1) {
        acc.x += __shfl_xor_sync(0xFFFFFFFFu, acc.x, o);
        acc.y += __shfl_xor_sync(0xFFFFFFFFu, acc.y, o);
        acc.z += __shfl_xor_sync(0xFFFFFFFFu, acc.z, o);
        acc.w += __shfl_xor_sync(0xFFFFFFFFu, acc.w, o);
    }
#pragma unroll
    for (int o = 16; o; o >>= 1)
        psum += __shfl_xor_sync(0xFFFFFFFFu, psum, o);
    float inv = (psum > 0.f) ? __frcp_rn(psum) : 0.f;
    float4 bb = *(const float4*)&b2[dg * 4];
    float4 val = make_float4(acc.x * inv + bb.x, acc.y * inv + bb.y,
                             acc.z * inv + bb.z, acc.w * inv + bb.w);

    float mm = fmaxf(fmaxf(val.x, val.y), fmaxf(val.z, val.w));
#pragma unroll
    for (int o = 1; o <= 2; o <<= 1)
        mm = fmaxf(mm, __shfl_xor_sync(0xFFFFFFFFu, mm, o));
    float es = __expf(val.x - mm) + __expf(val.y - mm) +
               __expf(val.z - mm) + __expf(val.w - mm);
#pragma unroll
    for (int o = 1; o <= 2; o <<= 1)
        es += __shfl_xor_sync(0xFFFFFFFFu, es, o);
    float lse = mm + logf(es);
    if (lane < 4) {
        *(float4*)&out[n * 16 + dg * 4] =
            make_float4(val.x - lse, val.y - lse, val.z - lse, val.w - lse);
    }
}

// ---------------- launcher ---------------------------------------------------
extern "C" void kernel_launch(void* const* d_in, const int* in_sizes, int n_in,
                              void* d_out, int out_size) {
    const float* features = (const float*)d_in[0];
    const int*   src      = (const int*)  d_in[1];
    const int*   dst      = (const int*)  d_in[2];
    const float* W1       = (const float*)d_in[3];
    const float* al1      = (const float*)d_in[4];
    const float* ar1      = (const float*)d_in[5];
    const float* b1       = (const float*)d_in[6];
    const float* W2       = (const float*)d_in[7];
    const float* al2      = (const float*)d_in[8];
    const float* ar2      = (const float*)d_in[9];
    const float* b2       = (const float*)d_in[10];
    float* out = (float*)d_out;

    int N = in_sizes[0] / 128;
    int E = in_sizes[1];
    int NB = (N + 1023) / 1024;
    int E4 = (E + 3) / 4;
    int gemm_smem = 2 * 128 * AS_STRIDE * (int)sizeof(__half);

    static int configured = 0;
    if (!configured) {
        cudaFuncSetAttribute(k_gemm1, cudaFuncAttributeMaxDynamicSharedMemorySize, gemm_smem);
        configured = 1;
    }

    k_prep<<<(N + 255) / 256, 256>>>(W1, N);
    k_hist<<<(E4 + 255) / 256, 256>>>(dst, E);
    k_scan<<<NB, 1024>>>(N, NB);
    k_scatter<<<(E4 + 255) / 256, 256>>>(src, dst, E);
    k_gemm1<<<(N + 127) / 128, 256, gemm_smem>>>(features, al1, ar1, N);
    k_agg1<<<(N + 7) / 8, 256>>>(b1, W2, al2, ar2, N);
    k_agg2<<<(N + 7) / 8, 256>>>(b2, out, N);
}